// round 1
// baseline (speedup 1.0000x reference)
#include <cuda_runtime.h>
#include <math.h>

#define DIM   768
#define QKV3  2304
#define HID   3072
#define NH    12
#define HD    64
#define SEQ   2048
#define BATCH 2
#define ROWS  (BATCH*SEQ)        /* 4096 */
#define LNEPS 1e-5f
#define ATT_SCALE 0.125f         /* 64^-0.5 */

/* ------------------------------------------------------------------ */
/* scratch (device globals; no allocation allowed)                     */
/* ------------------------------------------------------------------ */
__device__ float g_h  [ROWS * DIM];    /* LN1 out, reused for LN2 out  */
__device__ float g_qkv[ROWS * QKV3];
__device__ float g_y  [ROWS * DIM];    /* attention out                */
__device__ float g_x1 [ROWS * DIM];    /* residual after proj          */
__device__ float g_h2 [ROWS * HID];    /* gelu(fc1) out                */

/* ------------------------------------------------------------------ */
/* LayerNorm: one block per row of 768                                 */
/* ------------------------------------------------------------------ */
__global__ void __launch_bounds__(256) ln_kernel(
    const float* __restrict__ x, const float* __restrict__ g,
    const float* __restrict__ b, float* __restrict__ out)
{
    const int row = blockIdx.x;
    const int t   = threadIdx.x;
    const float* xp = x + (size_t)row * DIM;

    float vals[3];
    float s = 0.f, ss = 0.f;
#pragma unroll
    for (int i = 0; i < 3; i++) {
        float v = xp[t + i * 256];
        vals[i] = v; s += v; ss += v * v;
    }
#pragma unroll
    for (int o = 16; o > 0; o >>= 1) {
        s  += __shfl_xor_sync(0xffffffffu, s,  o);
        ss += __shfl_xor_sync(0xffffffffu, ss, o);
    }
    __shared__ float sm[8], sm2[8];
    __shared__ float s_mean, s_rstd;
    const int w = t >> 5;
    if ((t & 31) == 0) { sm[w] = s; sm2[w] = ss; }
    __syncthreads();
    if (t == 0) {
        float ts = 0.f, tss = 0.f;
#pragma unroll
        for (int i = 0; i < 8; i++) { ts += sm[i]; tss += sm2[i]; }
        float mean = ts * (1.0f / DIM);
        float var  = tss * (1.0f / DIM) - mean * mean;
        s_mean = mean;
        s_rstd = rsqrtf(var + LNEPS);
    }
    __syncthreads();
    const float mean = s_mean, rstd = s_rstd;
    float* op = out + (size_t)row * DIM;
#pragma unroll
    for (int i = 0; i < 3; i++) {
        int c = t + i * 256;
        op[c] = (vals[i] - mean) * rstd * g[c] + b[c];
    }
}

/* ------------------------------------------------------------------ */
/* NT GEMM: C[m,n] = sum_k A[m,k]*B[n,k], 64x64x16 tiles, 4x4 micro   */
/* EPI: 0 = plain, 1 = +bias +residual, 2 = +bias then exact GELU      */
/* ------------------------------------------------------------------ */
template <int EPI>
__global__ void __launch_bounds__(256) gemm_nt(
    const float* __restrict__ A, const float* __restrict__ B,
    const float* __restrict__ bias, const float* __restrict__ res,
    float* __restrict__ C, int M, int N, int K)
{
    __shared__ float As[16][64];
    __shared__ float Bs[16][64];

    const int t    = threadIdx.x;
    const int lrow = t & 63;            /* load row within tile        */
    const int kq   = (t >> 6) << 2;     /* 0,4,8,12                    */
    const int m0   = blockIdx.y << 6;
    const int n0   = blockIdx.x << 6;
    const int tx   = (t & 15) << 2;     /* n offset of micro-tile      */
    const int ty   = (t >> 4) << 2;     /* m offset of micro-tile      */

    const float* Ap = A + (size_t)(m0 + lrow) * K + kq;
    const float* Bp = B + (size_t)(n0 + lrow) * K + kq;

    float acc[4][4] = {};

    for (int k0 = 0; k0 < K; k0 += 16) {
        float4 a4 = *(const float4*)(Ap + k0);
        float4 b4 = *(const float4*)(Bp + k0);
        __syncthreads();
        As[kq + 0][lrow] = a4.x; As[kq + 1][lrow] = a4.y;
        As[kq + 2][lrow] = a4.z; As[kq + 3][lrow] = a4.w;
        Bs[kq + 0][lrow] = b4.x; Bs[kq + 1][lrow] = b4.y;
        Bs[kq + 2][lrow] = b4.z; Bs[kq + 3][lrow] = b4.w;
        __syncthreads();
#pragma unroll
        for (int k = 0; k < 16; k++) {
            float4 ra = *(const float4*)(&As[k][ty]);
            float4 rb = *(const float4*)(&Bs[k][tx]);
            float ar[4] = { ra.x, ra.y, ra.z, ra.w };
            float br[4] = { rb.x, rb.y, rb.z, rb.w };
#pragma unroll
            for (int i = 0; i < 4; i++)
#pragma unroll
                for (int j = 0; j < 4; j++)
                    acc[i][j] += ar[i] * br[j];
        }
    }

#pragma unroll
    for (int i = 0; i < 4; i++) {
        const int m = m0 + ty + i;
#pragma unroll
        for (int j = 0; j < 4; j++) {
            const int n = n0 + tx + j;
            float v = acc[i][j];
            if (EPI >= 1) v += bias[n];
            if (EPI == 1) v += res[(size_t)m * N + n];
            if (EPI == 2) v = 0.5f * v * (1.0f + erff(v * 0.70710678118654752f));
            C[(size_t)m * N + n] = v;
        }
    }
}

/* ------------------------------------------------------------------ */
/* Flash attention, fp32, key-mask. One block = (b,h, 64 queries).     */
/* Each of 64 threads owns one query row: Q[64] + O[64] in registers.  */
/* ------------------------------------------------------------------ */
__global__ void __launch_bounds__(64) attn_kernel(
    const float* __restrict__ qkv, const int* __restrict__ mask,
    float* __restrict__ y)
{
    __shared__ float Ks[64][68];        /* pad 68 -> tolerable STS conflicts */
    __shared__ float Vs[64][68];
    __shared__ int   msk[64];

    const int t  = threadIdx.x;
    const int bh = blockIdx.y;
    const int b  = bh / NH;
    const int h  = bh - b * NH;
    const int q  = (blockIdx.x << 6) + t;

    float Q[64], O[64];
    const float* qp = qkv + (size_t)(b * SEQ + q) * QKV3 + h * HD;
#pragma unroll
    for (int d = 0; d < 64; d++) { Q[d] = qp[d] * ATT_SCALE; O[d] = 0.f; }

    float mMax = -INFINITY, l = 0.f;

    for (int kt = 0; kt < SEQ; kt += 64) {
        const float* kp = qkv + (size_t)(b * SEQ + kt + t) * QKV3 + DIM + h * HD;
        const float* vp = kp + DIM;
        __syncthreads();
#pragma unroll
        for (int d = 0; d < 64; d += 4) {
            *(float4*)&Ks[t][d] = *(const float4*)(kp + d);
            *(float4*)&Vs[t][d] = *(const float4*)(vp + d);
        }
        msk[t] = mask[b * SEQ + kt + t];
        __syncthreads();

        for (int j = 0; j < 64; j++) {
            if (msk[j]) continue;       /* masked key: softmax weight 0 */
            float s0 = 0.f, s1 = 0.f, s2 = 0.f, s3 = 0.f;
#pragma unroll
            for (int d = 0; d < 64; d += 4) {
                float4 kv = *(const float4*)&Ks[j][d];
                s0 += Q[d + 0] * kv.x; s1 += Q[d + 1] * kv.y;
                s2 += Q[d + 2] * kv.z; s3 += Q[d + 3] * kv.w;
            }
            float s = (s0 + s1) + (s2 + s3);
            if (s > mMax) {             /* rare rescale (lazy online softmax) */
                float c = expf(mMax - s);   /* expf(-inf)=0 handles init */
                mMax = s;
                l *= c;
#pragma unroll
                for (int d = 0; d < 64; d++) O[d] *= c;
            }
            float p = expf(s - mMax);
            l += p;
#pragma unroll
            for (int d = 0; d < 64; d += 4) {
                float4 vv = *(const float4*)&Vs[j][d];
                O[d + 0] += p * vv.x; O[d + 1] += p * vv.y;
                O[d + 2] += p * vv.z; O[d + 3] += p * vv.w;
            }
        }
    }

    const float inv = 1.0f / l;
    float* yp = y + (size_t)(b * SEQ + q) * DIM + h * HD;
#pragma unroll
    for (int d = 0; d < 64; d++) yp[d] = O[d] * inv;
}

/* ------------------------------------------------------------------ */
/* launch                                                              */
/* ------------------------------------------------------------------ */
extern "C" void kernel_launch(void* const* d_in, const int* in_sizes, int n_in,
                              void* d_out, int out_size)
{
    (void)in_sizes; (void)n_in; (void)out_size;

    const float* x      = (const float*)d_in[0];
    const int*   mask   = (const int*)  d_in[1];
    const float* ln1_g  = (const float*)d_in[2];
    const float* ln1_b  = (const float*)d_in[3];
    const float* qkv_w  = (const float*)d_in[4];
    const float* proj_w = (const float*)d_in[5];
    const float* proj_b = (const float*)d_in[6];
    const float* ln2_g  = (const float*)d_in[7];
    const float* ln2_b  = (const float*)d_in[8];
    const float* fc1_w  = (const float*)d_in[9];
    const float* fc1_b  = (const float*)d_in[10];
    const float* fc2_w  = (const float*)d_in[11];
    const float* fc2_b  = (const float*)d_in[12];
    float* out = (float*)d_out;

    float *h, *qkv, *y, *x1, *h2;
    cudaGetSymbolAddress((void**)&h,   g_h);
    cudaGetSymbolAddress((void**)&qkv, g_qkv);
    cudaGetSymbolAddress((void**)&y,   g_y);
    cudaGetSymbolAddress((void**)&x1,  g_x1);
    cudaGetSymbolAddress((void**)&h2,  g_h2);

    /* 1. h = LN1(x) */
    ln_kernel<<<ROWS, 256>>>(x, ln1_g, ln1_b, h);

    /* 2. qkv = h @ qkv_w^T */
    gemm_nt<0><<<dim3(QKV3 / 64, ROWS / 64), 256>>>(
        h, qkv_w, nullptr, nullptr, qkv, ROWS, QKV3, DIM);

    /* 3. y = attention(qkv, mask) */
    attn_kernel<<<dim3(SEQ / 64, BATCH * NH), 64>>>(qkv, mask, y);

    /* 4. x1 = x + y @ proj_w^T + proj_b */
    gemm_nt<1><<<dim3(DIM / 64, ROWS / 64), 256>>>(
        y, proj_w, proj_b, x, x1, ROWS, DIM, DIM);

    /* 5. h = LN2(x1) */
    ln_kernel<<<ROWS, 256>>>(x1, ln2_g, ln2_b, h);

    /* 6. h2 = gelu(h @ fc1_w^T + fc1_b)   (exact GELU) */
    gemm_nt<2><<<dim3(HID / 64, ROWS / 64), 256>>>(
        h, fc1_w, fc1_b, nullptr, h2, ROWS, HID, DIM);

    /* 7. out = x1 + h2 @ fc2_w^T + fc2_b */
    gemm_nt<1><<<dim3(DIM / 64, ROWS / 64), 256>>>(
        h2, fc2_w, fc2_b, x1, out, ROWS, DIM, HID);
}

// round 7
// speedup vs baseline: 1.5598x; 1.5598x over previous
#include <cuda_runtime.h>
#include <math.h>

#define DIM   768
#define QKV3  2304
#define HID   3072
#define NH    12
#define HD    64
#define SEQ   2048
#define BATCH 2
#define ROWS  (BATCH*SEQ)        /* 4096 */
#define LNEPS 1e-5f
#define ATT_SCALE 0.125f         /* 64^-0.5 */

/* ------------------------------------------------------------------ */
/* scratch (device globals; no allocation allowed)                     */
/* ------------------------------------------------------------------ */
__device__ float g_h  [ROWS * DIM];    /* LN1 out, reused for LN2 out  */
__device__ float g_qkv[ROWS * QKV3];
__device__ float g_y  [ROWS * DIM];    /* attention out                */
__device__ float g_x1 [ROWS * DIM];    /* residual after proj          */
__device__ float g_h2 [ROWS * HID];    /* gelu(fc1) out                */

/* ------------------------------------------------------------------ */
/* LayerNorm: one block per row of 768                                 */
/* ------------------------------------------------------------------ */
__global__ void __launch_bounds__(256) ln_kernel(
    const float* __restrict__ x, const float* __restrict__ g,
    const float* __restrict__ b, float* __restrict__ out)
{
    const int row = blockIdx.x;
    const int t   = threadIdx.x;
    const float* xp = x + (size_t)row * DIM;

    float vals[3];
    float s = 0.f, ss = 0.f;
#pragma unroll
    for (int i = 0; i < 3; i++) {
        float v = xp[t + i * 256];
        vals[i] = v; s += v; ss += v * v;
    }
#pragma unroll
    for (int o = 16; o > 0; o >>= 1) {
        s  += __shfl_xor_sync(0xffffffffu, s,  o);
        ss += __shfl_xor_sync(0xffffffffu, ss, o);
    }
    __shared__ float sm[8], sm2[8];
    __shared__ float s_mean, s_rstd;
    const int w = t >> 5;
    if ((t & 31) == 0) { sm[w] = s; sm2[w] = ss; }
    __syncthreads();
    if (t == 0) {
        float ts = 0.f, tss = 0.f;
#pragma unroll
        for (int i = 0; i < 8; i++) { ts += sm[i]; tss += sm2[i]; }
        float mean = ts * (1.0f / DIM);
        float var  = tss * (1.0f / DIM) - mean * mean;
        s_mean = mean;
        s_rstd = rsqrtf(var + LNEPS);
    }
    __syncthreads();
    const float mean = s_mean, rstd = s_rstd;
    float* op = out + (size_t)row * DIM;
#pragma unroll
    for (int i = 0; i < 3; i++) {
        int c = t + i * 256;
        op[c] = (vals[i] - mean) * rstd * g[c] + b[c];
    }
}

/* ------------------------------------------------------------------ */
/* NT GEMM: C[m,n] = sum_k A[m,k]*B[n,k]                               */
/* 128x128 tile, 8x8 micro-tile, K-chunk 8, double-buffered smem.      */
/* EPI: 0 = plain, 1 = +bias +residual, 2 = +bias then exact GELU      */
/* ------------------------------------------------------------------ */
template <int EPI>
__global__ void __launch_bounds__(256) gemm_nt(
    const float* __restrict__ A, const float* __restrict__ B,
    const float* __restrict__ bias, const float* __restrict__ res,
    float* __restrict__ C, int M, int N, int K)
{
    __shared__ float As[2][8][128];
    __shared__ float Bs[2][8][128];

    const int t  = threadIdx.x;
    const int m0 = blockIdx.y << 7;
    const int n0 = blockIdx.x << 7;

    /* global loads: one float4 of A and one of B per thread per chunk */
    const int lr = t >> 1;            /* 0..127 row within tile        */
    const int lk = (t & 1) << 2;      /* 0 or 4                        */
    const float* Ap = A + (size_t)(m0 + lr) * K + lk;
    const float* Bp = B + (size_t)(n0 + lr) * K + lk;

    /* compute mapping: 16x16 thread grid, each owns rows {ty..ty+3,   */
    /* ty+64..ty+67} x cols {tx..tx+3, tx+64..tx+67}                   */
    const int tx = (t & 15) << 2;
    const int ty = ((t >> 4) & 15) << 2;

    float acc[8][8] = {};

    float4 pa = *(const float4*)Ap;
    float4 pb = *(const float4*)Bp;
    int buf = 0;
    As[0][lk + 0][lr] = pa.x; As[0][lk + 1][lr] = pa.y;
    As[0][lk + 2][lr] = pa.z; As[0][lk + 3][lr] = pa.w;
    Bs[0][lk + 0][lr] = pb.x; Bs[0][lk + 1][lr] = pb.y;
    Bs[0][lk + 2][lr] = pb.z; Bs[0][lk + 3][lr] = pb.w;
    __syncthreads();

    for (int k0 = 8; k0 <= K; k0 += 8) {
        const bool more = (k0 < K);
        if (more) {
            pa = *(const float4*)(Ap + k0);
            pb = *(const float4*)(Bp + k0);
        }
#pragma unroll
        for (int k = 0; k < 8; k++) {
            float4 a0 = *(const float4*)(&As[buf][k][ty]);
            float4 a1 = *(const float4*)(&As[buf][k][ty + 64]);
            float4 b0 = *(const float4*)(&Bs[buf][k][tx]);
            float4 b1 = *(const float4*)(&Bs[buf][k][tx + 64]);
            float ar[8] = { a0.x, a0.y, a0.z, a0.w, a1.x, a1.y, a1.z, a1.w };
            float br[8] = { b0.x, b0.y, b0.z, b0.w, b1.x, b1.y, b1.z, b1.w };
#pragma unroll
            for (int i = 0; i < 8; i++)
#pragma unroll
                for (int j = 0; j < 8; j++)
                    acc[i][j] += ar[i] * br[j];
        }
        if (!more) break;
        buf ^= 1;
        As[buf][lk + 0][lr] = pa.x; As[buf][lk + 1][lr] = pa.y;
        As[buf][lk + 2][lr] = pa.z; As[buf][lk + 3][lr] = pa.w;
        Bs[buf][lk + 0][lr] = pb.x; Bs[buf][lk + 1][lr] = pb.y;
        Bs[buf][lk + 2][lr] = pb.z; Bs[buf][lk + 3][lr] = pb.w;
        __syncthreads();
    }

    /* epilogue */
#pragma unroll
    for (int i = 0; i < 8; i++) {
        const int m = m0 + ((i < 4) ? (ty + i) : (ty + 60 + i)); /* +64+i-4 */
#pragma unroll
        for (int jh = 0; jh < 2; jh++) {
            const int n = n0 + tx + jh * 64;
            float4 v;
            v.x = acc[i][jh * 4 + 0]; v.y = acc[i][jh * 4 + 1];
            v.z = acc[i][jh * 4 + 2]; v.w = acc[i][jh * 4 + 3];
            if (EPI >= 1) {
                const float4 bb = *(const float4*)(bias + n);
                v.x += bb.x; v.y += bb.y; v.z += bb.z; v.w += bb.w;
            }
            if (EPI == 1) {
                const float4 rr = *(const float4*)(res + (size_t)m * N + n);
                v.x += rr.x; v.y += rr.y; v.z += rr.z; v.w += rr.w;
            }
            if (EPI == 2) {
                v.x = 0.5f * v.x * (1.0f + erff(v.x * 0.70710678f));
                v.y = 0.5f * v.y * (1.0f + erff(v.y * 0.70710678f));
                v.z = 0.5f * v.z * (1.0f + erff(v.z * 0.70710678f));
                v.w = 0.5f * v.w * (1.0f + erff(v.w * 0.70710678f));
            }
            *(float4*)(C + (size_t)m * N + n) = v;
        }
    }
}

/* ------------------------------------------------------------------ */
/* Flash attention, fp32, key-mask. One block = (b,h, 128 queries).    */
/* Each of 128 threads owns one query row: Q[64] + O[64] in registers. */
/* ------------------------------------------------------------------ */
__global__ void __launch_bounds__(128) attn_kernel(
    const float* __restrict__ qkv, const int* __restrict__ mask,
    float* __restrict__ y)
{
    __shared__ float Ks[64][68];
    __shared__ float Vs[64][68];
    __shared__ int   msk[64];

    const int t  = threadIdx.x;
    const int bh = blockIdx.y;
    const int b  = bh / NH;
    const int h  = bh - b * NH;
    const int q  = (blockIdx.x << 7) + t;

    float Q[64], O[64];
    const float* qp = qkv + (size_t)(b * SEQ + q) * QKV3 + h * HD;
#pragma unroll
    for (int d = 0; d < 64; d += 4) {
        float4 qv = *(const float4*)(qp + d);
        Q[d + 0] = qv.x * ATT_SCALE; Q[d + 1] = qv.y * ATT_SCALE;
        Q[d + 2] = qv.z * ATT_SCALE; Q[d + 3] = qv.w * ATT_SCALE;
        O[d + 0] = 0.f; O[d + 1] = 0.f; O[d + 2] = 0.f; O[d + 3] = 0.f;
    }

    float mMax = -INFINITY, l = 0.f;

    for (int kt = 0; kt < SEQ; kt += 64) {
        const int krow = t & 63;          /* key row this thread copies */
        const int half = (t >> 6) << 5;   /* 0 or 32 (d-offset)         */
        const float* kp = qkv + (size_t)(b * SEQ + kt + krow) * QKV3
                              + DIM + h * HD + half;
        const float* vp = kp + DIM;
        __syncthreads();
#pragma unroll
        for (int d = 0; d < 32; d += 4) {
            *(float4*)&Ks[krow][half + d] = *(const float4*)(kp + d);
            *(float4*)&Vs[krow][half + d] = *(const float4*)(vp + d);
        }
        if (t < 64) msk[t] = mask[b * SEQ + kt + t];
        __syncthreads();

        for (int j = 0; j < 64; j++) {
            if (msk[j]) continue;       /* masked key: softmax weight 0 */
            float s0 = 0.f, s1 = 0.f, s2 = 0.f, s3 = 0.f;
#pragma unroll
            for (int d = 0; d < 64; d += 4) {
                float4 kv = *(const float4*)&Ks[j][d];
                s0 += Q[d + 0] * kv.x; s1 += Q[d + 1] * kv.y;
                s2 += Q[d + 2] * kv.z; s3 += Q[d + 3] * kv.w;
            }
            float s = (s0 + s1) + (s2 + s3);
            if (s > mMax) {             /* rare rescale (lazy online softmax) */
                float c = __expf(mMax - s);  /* __expf(-inf)=0 handles init */
                mMax = s;
                l *= c;
#pragma unroll
                for (int d = 0; d < 64; d++) O[d] *= c;
            }
            float p = __expf(s - mMax);
            l += p;
#pragma unroll
            for (int d = 0; d < 64; d += 4) {
                float4 vv = *(const float4*)&Vs[j][d];
                O[d + 0] += p * vv.x; O[d + 1] += p * vv.y;
                O[d + 2] += p * vv.z; O[d + 3] += p * vv.w;
            }
        }
    }

    const float inv = 1.0f / l;
    float* yp = y + (size_t)(b * SEQ + q) * DIM + h * HD;
#pragma unroll
    for (int d = 0; d < 64; d += 4) {
        float4 ov;
        ov.x = O[d + 0] * inv; ov.y = O[d + 1] * inv;
        ov.z = O[d + 2] * inv; ov.w = O[d + 3] * inv;
        *(float4*)(yp + d) = ov;
    }
}

/* ------------------------------------------------------------------ */
/* launch                                                              */
/* ------------------------------------------------------------------ */
extern "C" void kernel_launch(void* const* d_in, const int* in_sizes, int n_in,
                              void* d_out, int out_size)
{
    (void)in_sizes; (void)n_in; (void)out_size;

    const float* x      = (const float*)d_in[0];
    const int*   mask   = (const int*)  d_in[1];
    const float* ln1_g  = (const float*)d_in[2];
    const float* ln1_b  = (const float*)d_in[3];
    const float* qkv_w  = (const float*)d_in[4];
    const float* proj_w = (const float*)d_in[5];
    const float* proj_b = (const float*)d_in[6];
    const float* ln2_g  = (const float*)d_in[7];
    const float* ln2_b  = (const float*)d_in[8];
    const float* fc1_w  = (const float*)d_in[9];
    const float* fc1_b  = (const float*)d_in[10];
    const float* fc2_w  = (const float*)d_in[11];
    const float* fc2_b  = (const float*)d_in[12];
    float* out = (float*)d_out;

    float *h, *qkv, *y, *x1, *h2;
    cudaGetSymbolAddress((void**)&h,   g_h);
    cudaGetSymbolAddress((void**)&qkv, g_qkv);
    cudaGetSymbolAddress((void**)&y,   g_y);
    cudaGetSymbolAddress((void**)&x1,  g_x1);
    cudaGetSymbolAddress((void**)&h2,  g_h2);

    /* 1. h = LN1(x) */
    ln_kernel<<<ROWS, 256>>>(x, ln1_g, ln1_b, h);

    /* 2. qkv = h @ qkv_w^T */
    gemm_nt<0><<<dim3(QKV3 / 128, ROWS / 128), 256>>>(
        h, qkv_w, nullptr, nullptr, qkv, ROWS, QKV3, DIM);

    /* 3. y = attention(qkv, mask) */
    attn_kernel<<<dim3(SEQ / 128, BATCH * NH), 128>>>(qkv, mask, y);

    /* 4. x1 = x + y @ proj_w^T + proj_b */
    gemm_nt<1><<<dim3(DIM / 128, ROWS / 128), 256>>>(
        y, proj_w, proj_b, x, x1, ROWS, DIM, DIM);

    /* 5. h = LN2(x1) */
    ln_kernel<<<ROWS, 256>>>(x1, ln2_g, ln2_b, h);

    /* 6. h2 = gelu(h @ fc1_w^T + fc1_b)   (exact GELU) */
    gemm_nt<2><<<dim3(HID / 128, ROWS / 128), 256>>>(
        h, fc1_w, fc1_b, nullptr, h2, ROWS, HID, DIM);

    /* 7. out = x1 + h2 @ fc2_w^T + fc2_b */
    gemm_nt<1><<<dim3(DIM / 128, ROWS / 128), 256>>>(
        h2, fc2_w, fc2_b, x1, out, ROWS, DIM, HID);
}

// round 9
// speedup vs baseline: 2.4242x; 1.5541x over previous
#include <cuda_runtime.h>
#include <math.h>
#include <stdint.h>

#define DIM   768
#define QKV3  2304
#define HID   3072
#define NH    12
#define HD    64
#define SEQ   2048
#define BATCH 2
#define ROWS  (BATCH*SEQ)        /* 4096 */
#define LNEPS 1e-5f
#define ATT_SCALE 0.125f         /* 64^-0.5 */

/* ------------------------------------------------------------------ */
/* scratch (device globals; no allocation allowed)                     */
/* ------------------------------------------------------------------ */
__device__ float g_h  [ROWS * DIM];
__device__ float g_qkv[ROWS * QKV3];
__device__ float g_y  [ROWS * DIM];
__device__ float g_x1 [ROWS * DIM];
__device__ float g_h2 [ROWS * HID];

/* ------------------------------------------------------------------ */
/* LayerNorm: one block per row of 768                                 */
/* ------------------------------------------------------------------ */
__global__ void __launch_bounds__(256) ln_kernel(
    const float* __restrict__ x, const float* __restrict__ g,
    const float* __restrict__ b, float* __restrict__ out)
{
    const int row = blockIdx.x;
    const int t   = threadIdx.x;
    const float* xp = x + (size_t)row * DIM;

    float vals[3];
    float s = 0.f, ss = 0.f;
#pragma unroll
    for (int i = 0; i < 3; i++) {
        float v = xp[t + i * 256];
        vals[i] = v; s += v; ss += v * v;
    }
#pragma unroll
    for (int o = 16; o > 0; o >>= 1) {
        s  += __shfl_xor_sync(0xffffffffu, s,  o);
        ss += __shfl_xor_sync(0xffffffffu, ss, o);
    }
    __shared__ float sm[8], sm2[8];
    __shared__ float s_mean, s_rstd;
    const int w = t >> 5;
    if ((t & 31) == 0) { sm[w] = s; sm2[w] = ss; }
    __syncthreads();
    if (t == 0) {
        float ts = 0.f, tss = 0.f;
#pragma unroll
        for (int i = 0; i < 8; i++) { ts += sm[i]; tss += sm2[i]; }
        float mean = ts * (1.0f / DIM);
        float var  = tss * (1.0f / DIM) - mean * mean;
        s_mean = mean;
        s_rstd = rsqrtf(var + LNEPS);
    }
    __syncthreads();
    const float mean = s_mean, rstd = s_rstd;
    float* op = out + (size_t)row * DIM;
#pragma unroll
    for (int i = 0; i < 3; i++) {
        int c = t + i * 256;
        op[c] = (vals[i] - mean) * rstd * g[c] + b[c];
    }
}

/* ------------------------------------------------------------------ */
/* TF32 tensor-core GEMM (mma.sync m16n8k8).                           */
/* C[m,n] = sum_k A[m,k]*B[n,k]; A row-major [M,K], B row-major [N,K]. */
/* 128x128 CTA tile, 8 warps (2x4), warp tile 64x32, BK=16, dbl-buf.   */
/* EPI: 0 = plain, 1 = +bias +residual, 2 = +bias then exact GELU      */
/* ------------------------------------------------------------------ */
__device__ __forceinline__ uint32_t f2tf32(float x) {
    uint32_t r;
    asm("cvt.rna.tf32.f32 %0, %1;" : "=r"(r) : "f"(x));
    return r;
}

#define SMSTRIDE 136   /* 128 + 8 pad: stride%32==8 -> conflict-free frag LDS */

template <int EPI>
__global__ void __launch_bounds__(256) gemm_mma(
    const float* __restrict__ A, const float* __restrict__ B,
    const float* __restrict__ bias, const float* __restrict__ res,
    float* __restrict__ C, int M, int N, int K)
{
    __shared__ uint32_t As[2][16][SMSTRIDE];   /* [buf][k][m] */
    __shared__ uint32_t Bs[2][16][SMSTRIDE];   /* [buf][k][n] */

    const int t    = threadIdx.x;
    const int lane = t & 31;
    const int grp  = lane >> 2;      /* 0..7  */
    const int qid  = lane & 3;       /* 0..3  */
    const int warp = t >> 5;         /* 0..7  */
    const int wm   = warp >> 2;      /* 0..1  */
    const int wn   = warp & 3;       /* 0..3  */

    const int m0 = blockIdx.y << 7;
    const int n0 = blockIdx.x << 7;

    /* global load mapping: thread covers rows lr & lr+64, k window lk..lk+3 */
    const int lr = t >> 2;           /* 0..63 */
    const int lk = (t & 3) << 2;     /* 0,4,8,12 */
    const float* Ap0 = A + (size_t)(m0 + lr) * K + lk;
    const float* Ap1 = A + (size_t)(m0 + lr + 64) * K + lk;
    const float* Bp0 = B + (size_t)(n0 + lr) * K + lk;
    const float* Bp1 = B + (size_t)(n0 + lr + 64) * K + lk;

    float acc[4][4][4];
#pragma unroll
    for (int i = 0; i < 4; i++)
#pragma unroll
        for (int j = 0; j < 4; j++)
#pragma unroll
            for (int r = 0; r < 4; r++) acc[i][j][r] = 0.f;

    float4 pa0 = *(const float4*)Ap0;
    float4 pa1 = *(const float4*)Ap1;
    float4 pb0 = *(const float4*)Bp0;
    float4 pb1 = *(const float4*)Bp1;

    int buf = 0;
    {
        As[0][lk + 0][lr]      = f2tf32(pa0.x);
        As[0][lk + 1][lr]      = f2tf32(pa0.y);
        As[0][lk + 2][lr]      = f2tf32(pa0.z);
        As[0][lk + 3][lr]      = f2tf32(pa0.w);
        As[0][lk + 0][lr + 64] = f2tf32(pa1.x);
        As[0][lk + 1][lr + 64] = f2tf32(pa1.y);
        As[0][lk + 2][lr + 64] = f2tf32(pa1.z);
        As[0][lk + 3][lr + 64] = f2tf32(pa1.w);
        Bs[0][lk + 0][lr]      = f2tf32(pb0.x);
        Bs[0][lk + 1][lr]      = f2tf32(pb0.y);
        Bs[0][lk + 2][lr]      = f2tf32(pb0.z);
        Bs[0][lk + 3][lr]      = f2tf32(pb0.w);
        Bs[0][lk + 0][lr + 64] = f2tf32(pb1.x);
        Bs[0][lk + 1][lr + 64] = f2tf32(pb1.y);
        Bs[0][lk + 2][lr + 64] = f2tf32(pb1.z);
        Bs[0][lk + 3][lr + 64] = f2tf32(pb1.w);
    }
    __syncthreads();

    for (int k0 = 16; k0 <= K; k0 += 16) {
        const bool more = (k0 < K);
        if (more) {
            pa0 = *(const float4*)(Ap0 + k0);
            pa1 = *(const float4*)(Ap1 + k0);
            pb0 = *(const float4*)(Bp0 + k0);
            pb1 = *(const float4*)(Bp1 + k0);
        }

#pragma unroll
        for (int ks = 0; ks < 2; ks++) {
            const int kk = ks << 3;
            uint32_t af[4][4], bfr[4][2];
#pragma unroll
            for (int mt = 0; mt < 4; mt++) {
                const int mb = wm * 64 + mt * 16 + grp;
                af[mt][0] = As[buf][kk + qid][mb];
                af[mt][1] = As[buf][kk + qid][mb + 8];
                af[mt][2] = As[buf][kk + qid + 4][mb];
                af[mt][3] = As[buf][kk + qid + 4][mb + 8];
            }
#pragma unroll
            for (int nt = 0; nt < 4; nt++) {
                const int nb = wn * 32 + nt * 8 + grp;
                bfr[nt][0] = Bs[buf][kk + qid][nb];
                bfr[nt][1] = Bs[buf][kk + qid + 4][nb];
            }
#pragma unroll
            for (int mt = 0; mt < 4; mt++)
#pragma unroll
                for (int nt = 0; nt < 4; nt++) {
                    asm volatile(
                        "mma.sync.aligned.m16n8k8.row.col.f32.tf32.tf32.f32 "
                        "{%0,%1,%2,%3}, {%4,%5,%6,%7}, {%8,%9}, {%0,%1,%2,%3};\n"
                        : "+f"(acc[mt][nt][0]), "+f"(acc[mt][nt][1]),
                          "+f"(acc[mt][nt][2]), "+f"(acc[mt][nt][3])
                        : "r"(af[mt][0]), "r"(af[mt][1]),
                          "r"(af[mt][2]), "r"(af[mt][3]),
                          "r"(bfr[nt][0]), "r"(bfr[nt][1]));
                }
        }

        if (!more) break;
        buf ^= 1;
        As[buf][lk + 0][lr]      = f2tf32(pa0.x);
        As[buf][lk + 1][lr]      = f2tf32(pa0.y);
        As[buf][lk + 2][lr]      = f2tf32(pa0.z);
        As[buf][lk + 3][lr]      = f2tf32(pa0.w);
        As[buf][lk + 0][lr + 64] = f2tf32(pa1.x);
        As[buf][lk + 1][lr + 64] = f2tf32(pa1.y);
        As[buf][lk + 2][lr + 64] = f2tf32(pa1.z);
        As[buf][lk + 3][lr + 64] = f2tf32(pa1.w);
        Bs[buf][lk + 0][lr]      = f2tf32(pb0.x);
        Bs[buf][lk + 1][lr]      = f2tf32(pb0.y);
        Bs[buf][lk + 2][lr]      = f2tf32(pb0.z);
        Bs[buf][lk + 3][lr]      = f2tf32(pb0.w);
        Bs[buf][lk + 0][lr + 64] = f2tf32(pb1.x);
        Bs[buf][lk + 1][lr + 64] = f2tf32(pb1.y);
        Bs[buf][lk + 2][lr + 64] = f2tf32(pb1.z);
        Bs[buf][lk + 3][lr + 64] = f2tf32(pb1.w);
        __syncthreads();
    }

    /* epilogue: c0:(grp,2q) c1:(grp,2q+1) c2:(grp+8,2q) c3:(grp+8,2q+1) */
#pragma unroll
    for (int mt = 0; mt < 4; mt++) {
        const int r0 = m0 + wm * 64 + mt * 16 + grp;
        const int r1 = r0 + 8;
#pragma unroll
        for (int nt = 0; nt < 4; nt++) {
            const int n = n0 + wn * 32 + nt * 8 + (qid << 1);
            float2 v0, v1;
            v0.x = acc[mt][nt][0]; v0.y = acc[mt][nt][1];
            v1.x = acc[mt][nt][2]; v1.y = acc[mt][nt][3];
            if (EPI >= 1) {
                const float2 bb = *(const float2*)(bias + n);
                v0.x += bb.x; v0.y += bb.y;
                v1.x += bb.x; v1.y += bb.y;
            }
            if (EPI == 1) {
                const float2 q0 = *(const float2*)(res + (size_t)r0 * N + n);
                const float2 q1 = *(const float2*)(res + (size_t)r1 * N + n);
                v0.x += q0.x; v0.y += q0.y;
                v1.x += q1.x; v1.y += q1.y;
            }
            if (EPI == 2) {
                v0.x = 0.5f * v0.x * (1.0f + erff(v0.x * 0.70710678f));
                v0.y = 0.5f * v0.y * (1.0f + erff(v0.y * 0.70710678f));
                v1.x = 0.5f * v1.x * (1.0f + erff(v1.x * 0.70710678f));
                v1.y = 0.5f * v1.y * (1.0f + erff(v1.y * 0.70710678f));
            }
            *(float2*)(C + (size_t)r0 * N + n) = v0;
            *(float2*)(C + (size_t)r1 * N + n) = v1;
        }
    }
}

/* ------------------------------------------------------------------ */
/* Flash attention, fp32, key-mask (unchanged from R7 passer).         */
/* ------------------------------------------------------------------ */
__global__ void __launch_bounds__(128) attn_kernel(
    const float* __restrict__ qkv, const int* __restrict__ mask,
    float* __restrict__ y)
{
    __shared__ float Ks[64][68];
    __shared__ float Vs[64][68];
    __shared__ int   msk[64];

    const int t  = threadIdx.x;
    const int bh = blockIdx.y;
    const int b  = bh / NH;
    const int h  = bh - b * NH;
    const int q  = (blockIdx.x << 7) + t;

    float Q[64], O[64];
    const float* qp = qkv + (size_t)(b * SEQ + q) * QKV3 + h * HD;
#pragma unroll
    for (int d = 0; d < 64; d += 4) {
        float4 qv = *(const float4*)(qp + d);
        Q[d + 0] = qv.x * ATT_SCALE; Q[d + 1] = qv.y * ATT_SCALE;
        Q[d + 2] = qv.z * ATT_SCALE; Q[d + 3] = qv.w * ATT_SCALE;
        O[d + 0] = 0.f; O[d + 1] = 0.f; O[d + 2] = 0.f; O[d + 3] = 0.f;
    }

    float mMax = -INFINITY, l = 0.f;

    for (int kt = 0; kt < SEQ; kt += 64) {
        const int krow = t & 63;
        const int half = (t >> 6) << 5;
        const float* kp = qkv + (size_t)(b * SEQ + kt + krow) * QKV3
                              + DIM + h * HD + half;
        const float* vp = kp + DIM;
        __syncthreads();
#pragma unroll
        for (int d = 0; d < 32; d += 4) {
            *(float4*)&Ks[krow][half + d] = *(const float4*)(kp + d);
            *(float4*)&Vs[krow][half + d] = *(const float4*)(vp + d);
        }
        if (t < 64) msk[t] = mask[b * SEQ + kt + t];
        __syncthreads();

        for (int j = 0; j < 64; j++) {
            if (msk[j]) continue;
            float s0 = 0.f, s1 = 0.f, s2 = 0.f, s3 = 0.f;
#pragma unroll
            for (int d = 0; d < 64; d += 4) {
                float4 kv = *(const float4*)&Ks[j][d];
                s0 += Q[d + 0] * kv.x; s1 += Q[d + 1] * kv.y;
                s2 += Q[d + 2] * kv.z; s3 += Q[d + 3] * kv.w;
            }
            float s = (s0 + s1) + (s2 + s3);
            if (s > mMax) {
                float c = __expf(mMax - s);
                mMax = s;
                l *= c;
#pragma unroll
                for (int d = 0; d < 64; d++) O[d] *= c;
            }
            float p = __expf(s - mMax);
            l += p;
#pragma unroll
            for (int d = 0; d < 64; d += 4) {
                float4 vv = *(const float4*)&Vs[j][d];
                O[d + 0] += p * vv.x; O[d + 1] += p * vv.y;
                O[d + 2] += p * vv.z; O[d + 3] += p * vv.w;
            }
        }
    }

    const float inv = 1.0f / l;
    float* yp = y + (size_t)(b * SEQ + q) * DIM + h * HD;
#pragma unroll
    for (int d = 0; d < 64; d += 4) {
        float4 ov;
        ov.x = O[d + 0] * inv; ov.y = O[d + 1] * inv;
        ov.z = O[d + 2] * inv; ov.w = O[d + 3] * inv;
        *(float4*)(yp + d) = ov;
    }
}

/* ------------------------------------------------------------------ */
/* launch                                                              */
/* ------------------------------------------------------------------ */
extern "C" void kernel_launch(void* const* d_in, const int* in_sizes, int n_in,
                              void* d_out, int out_size)
{
    (void)in_sizes; (void)n_in; (void)out_size;

    const float* x      = (const float*)d_in[0];
    const int*   mask   = (const int*)  d_in[1];
    const float* ln1_g  = (const float*)d_in[2];
    const float* ln1_b  = (const float*)d_in[3];
    const float* qkv_w  = (const float*)d_in[4];
    const float* proj_w = (const float*)d_in[5];
    const float* proj_b = (const float*)d_in[6];
    const float* ln2_g  = (const float*)d_in[7];
    const float* ln2_b  = (const float*)d_in[8];
    const float* fc1_w  = (const float*)d_in[9];
    const float* fc1_b  = (const float*)d_in[10];
    const float* fc2_w  = (const float*)d_in[11];
    const float* fc2_b  = (const float*)d_in[12];
    float* out = (float*)d_out;

    float *h, *qkv, *y, *x1, *h2;
    cudaGetSymbolAddress((void**)&h,   g_h);
    cudaGetSymbolAddress((void**)&qkv, g_qkv);
    cudaGetSymbolAddress((void**)&y,   g_y);
    cudaGetSymbolAddress((void**)&x1,  g_x1);
    cudaGetSymbolAddress((void**)&h2,  g_h2);

    /* 1. h = LN1(x) */
    ln_kernel<<<ROWS, 256>>>(x, ln1_g, ln1_b, h);

    /* 2. qkv = h @ qkv_w^T */
    gemm_mma<0><<<dim3(QKV3 / 128, ROWS / 128), 256>>>(
        h, qkv_w, nullptr, nullptr, qkv, ROWS, QKV3, DIM);

    /* 3. y = attention(qkv, mask) */
    attn_kernel<<<dim3(SEQ / 128, BATCH * NH), 128>>>(qkv, mask, y);

    /* 4. x1 = x + y @ proj_w^T + proj_b */
    gemm_mma<1><<<dim3(DIM / 128, ROWS / 128), 256>>>(
        y, proj_w, proj_b, x, x1, ROWS, DIM, DIM);

    /* 5. h = LN2(x1) */
    ln_kernel<<<ROWS, 256>>>(x1, ln2_g, ln2_b, h);

    /* 6. h2 = gelu(h @ fc1_w^T + fc1_b)   (exact GELU) */
    gemm_mma<2><<<dim3(HID / 128, ROWS / 128), 256>>>(
        h, fc1_w, fc1_b, nullptr, h2, ROWS, HID, DIM);

    /* 7. out = x1 + h2 @ fc2_w^T + fc2_b */
    gemm_mma<1><<<dim3(DIM / 128, ROWS / 128), 256>>>(
        h2, fc2_w, fc2_b, x1, out, ROWS, DIM, HID);
}

// round 11
// speedup vs baseline: 3.0236x; 1.2472x over previous
#include <cuda_runtime.h>
#include <math.h>
#include <stdint.h>

#define DIM   768
#define QKV3  2304
#define HID   3072
#define NH    12
#define HD    64
#define SEQ   2048
#define BATCH 2
#define ROWS  (BATCH*SEQ)        /* 4096 */
#define LNEPS 1e-5f
#define ATT_SCALE 0.125f         /* 64^-0.5 */

/* ------------------------------------------------------------------ */
/* scratch (device globals; no allocation allowed)                     */
/* ------------------------------------------------------------------ */
__device__ float g_h  [ROWS * DIM];
__device__ float g_qkv[ROWS * QKV3];
__device__ float g_y  [ROWS * DIM];
__device__ float g_x1 [ROWS * DIM];
__device__ float g_h2 [ROWS * HID];

__device__ __forceinline__ uint32_t f2tf32(float x) {
    uint32_t r;
    asm("cvt.rna.tf32.f32 %0, %1;" : "=r"(r) : "f"(x));
    return r;
}

__device__ __forceinline__ void mma_tf32(float* c,
    uint32_t a0, uint32_t a1, uint32_t a2, uint32_t a3,
    uint32_t b0, uint32_t b1)
{
    asm volatile(
        "mma.sync.aligned.m16n8k8.row.col.f32.tf32.tf32.f32 "
        "{%0,%1,%2,%3}, {%4,%5,%6,%7}, {%8,%9}, {%0,%1,%2,%3};\n"
        : "+f"(c[0]), "+f"(c[1]), "+f"(c[2]), "+f"(c[3])
        : "r"(a0), "r"(a1), "r"(a2), "r"(a3), "r"(b0), "r"(b1));
}

/* ------------------------------------------------------------------ */
/* LayerNorm: one block per row of 768                                 */
/* ------------------------------------------------------------------ */
__global__ void __launch_bounds__(256) ln_kernel(
    const float* __restrict__ x, const float* __restrict__ g,
    const float* __restrict__ b, float* __restrict__ out)
{
    const int row = blockIdx.x;
    const int t   = threadIdx.x;
    const float* xp = x + (size_t)row * DIM;

    float vals[3];
    float s = 0.f, ss = 0.f;
#pragma unroll
    for (int i = 0; i < 3; i++) {
        float v = xp[t + i * 256];
        vals[i] = v; s += v; ss += v * v;
    }
#pragma unroll
    for (int o = 16; o > 0; o >>= 1) {
        s  += __shfl_xor_sync(0xffffffffu, s,  o);
        ss += __shfl_xor_sync(0xffffffffu, ss, o);
    }
    __shared__ float sm[8], sm2[8];
    __shared__ float s_mean, s_rstd;
    const int w = t >> 5;
    if ((t & 31) == 0) { sm[w] = s; sm2[w] = ss; }
    __syncthreads();
    if (t == 0) {
        float ts = 0.f, tss = 0.f;
#pragma unroll
        for (int i = 0; i < 8; i++) { ts += sm[i]; tss += sm2[i]; }
        float mean = ts * (1.0f / DIM);
        float var  = tss * (1.0f / DIM) - mean * mean;
        s_mean = mean;
        s_rstd = rsqrtf(var + LNEPS);
    }
    __syncthreads();
    const float mean = s_mean, rstd = s_rstd;
    float* op = out + (size_t)row * DIM;
#pragma unroll
    for (int i = 0; i < 3; i++) {
        int c = t + i * 256;
        op[c] = (vals[i] - mean) * rstd * g[c] + b[c];
    }
}

/* ------------------------------------------------------------------ */
/* TF32 tensor-core GEMM (unchanged from R9 passer).                   */
/* ------------------------------------------------------------------ */
#define SMSTRIDE 136

template <int EPI>
__global__ void __launch_bounds__(256) gemm_mma(
    const float* __restrict__ A, const float* __restrict__ B,
    const float* __restrict__ bias, const float* __restrict__ res,
    float* __restrict__ C, int M, int N, int K)
{
    __shared__ uint32_t As[2][16][SMSTRIDE];
    __shared__ uint32_t Bs[2][16][SMSTRIDE];

    const int t    = threadIdx.x;
    const int lane = t & 31;
    const int grp  = lane >> 2;
    const int qid  = lane & 3;
    const int warp = t >> 5;
    const int wm   = warp >> 2;
    const int wn   = warp & 3;

    const int m0 = blockIdx.y << 7;
    const int n0 = blockIdx.x << 7;

    const int lr = t >> 2;
    const int lk = (t & 3) << 2;
    const float* Ap0 = A + (size_t)(m0 + lr) * K + lk;
    const float* Ap1 = A + (size_t)(m0 + lr + 64) * K + lk;
    const float* Bp0 = B + (size_t)(n0 + lr) * K + lk;
    const float* Bp1 = B + (size_t)(n0 + lr + 64) * K + lk;

    float acc[4][4][4];
#pragma unroll
    for (int i = 0; i < 4; i++)
#pragma unroll
        for (int j = 0; j < 4; j++)
#pragma unroll
            for (int r = 0; r < 4; r++) acc[i][j][r] = 0.f;

    float4 pa0 = *(const float4*)Ap0;
    float4 pa1 = *(const float4*)Ap1;
    float4 pb0 = *(const float4*)Bp0;
    float4 pb1 = *(const float4*)Bp1;

    int buf = 0;
    {
        As[0][lk + 0][lr]      = f2tf32(pa0.x);
        As[0][lk + 1][lr]      = f2tf32(pa0.y);
        As[0][lk + 2][lr]      = f2tf32(pa0.z);
        As[0][lk + 3][lr]      = f2tf32(pa0.w);
        As[0][lk + 0][lr + 64] = f2tf32(pa1.x);
        As[0][lk + 1][lr + 64] = f2tf32(pa1.y);
        As[0][lk + 2][lr + 64] = f2tf32(pa1.z);
        As[0][lk + 3][lr + 64] = f2tf32(pa1.w);
        Bs[0][lk + 0][lr]      = f2tf32(pb0.x);
        Bs[0][lk + 1][lr]      = f2tf32(pb0.y);
        Bs[0][lk + 2][lr]      = f2tf32(pb0.z);
        Bs[0][lk + 3][lr]      = f2tf32(pb0.w);
        Bs[0][lk + 0][lr + 64] = f2tf32(pb1.x);
        Bs[0][lk + 1][lr + 64] = f2tf32(pb1.y);
        Bs[0][lk + 2][lr + 64] = f2tf32(pb1.z);
        Bs[0][lk + 3][lr + 64] = f2tf32(pb1.w);
    }
    __syncthreads();

    for (int k0 = 16; k0 <= K; k0 += 16) {
        const bool more = (k0 < K);
        if (more) {
            pa0 = *(const float4*)(Ap0 + k0);
            pa1 = *(const float4*)(Ap1 + k0);
            pb0 = *(const float4*)(Bp0 + k0);
            pb1 = *(const float4*)(Bp1 + k0);
        }

#pragma unroll
        for (int ks = 0; ks < 2; ks++) {
            const int kk = ks << 3;
            uint32_t af[4][4], bfr[4][2];
#pragma unroll
            for (int mt = 0; mt < 4; mt++) {
                const int mb = wm * 64 + mt * 16 + grp;
                af[mt][0] = As[buf][kk + qid][mb];
                af[mt][1] = As[buf][kk + qid][mb + 8];
                af[mt][2] = As[buf][kk + qid + 4][mb];
                af[mt][3] = As[buf][kk + qid + 4][mb + 8];
            }
#pragma unroll
            for (int nt = 0; nt < 4; nt++) {
                const int nb = wn * 32 + nt * 8 + grp;
                bfr[nt][0] = Bs[buf][kk + qid][nb];
                bfr[nt][1] = Bs[buf][kk + qid + 4][nb];
            }
#pragma unroll
            for (int mt = 0; mt < 4; mt++)
#pragma unroll
                for (int nt = 0; nt < 4; nt++)
                    mma_tf32(acc[mt][nt], af[mt][0], af[mt][1], af[mt][2],
                             af[mt][3], bfr[nt][0], bfr[nt][1]);
        }

        if (!more) break;
        buf ^= 1;
        As[buf][lk + 0][lr]      = f2tf32(pa0.x);
        As[buf][lk + 1][lr]      = f2tf32(pa0.y);
        As[buf][lk + 2][lr]      = f2tf32(pa0.z);
        As[buf][lk + 3][lr]      = f2tf32(pa0.w);
        As[buf][lk + 0][lr + 64] = f2tf32(pa1.x);
        As[buf][lk + 1][lr + 64] = f2tf32(pa1.y);
        As[buf][lk + 2][lr + 64] = f2tf32(pa1.z);
        As[buf][lk + 3][lr + 64] = f2tf32(pa1.w);
        Bs[buf][lk + 0][lr]      = f2tf32(pb0.x);
        Bs[buf][lk + 1][lr]      = f2tf32(pb0.y);
        Bs[buf][lk + 2][lr]      = f2tf32(pb0.z);
        Bs[buf][lk + 3][lr]      = f2tf32(pb0.w);
        Bs[buf][lk + 0][lr + 64] = f2tf32(pb1.x);
        Bs[buf][lk + 1][lr + 64] = f2tf32(pb1.y);
        Bs[buf][lk + 2][lr + 64] = f2tf32(pb1.z);
        Bs[buf][lk + 3][lr + 64] = f2tf32(pb1.w);
        __syncthreads();
    }

#pragma unroll
    for (int mt = 0; mt < 4; mt++) {
        const int r0 = m0 + wm * 64 + mt * 16 + grp;
        const int r1 = r0 + 8;
#pragma unroll
        for (int nt = 0; nt < 4; nt++) {
            const int n = n0 + wn * 32 + nt * 8 + (qid << 1);
            float2 v0, v1;
            v0.x = acc[mt][nt][0]; v0.y = acc[mt][nt][1];
            v1.x = acc[mt][nt][2]; v1.y = acc[mt][nt][3];
            if (EPI >= 1) {
                const float2 bb = *(const float2*)(bias + n);
                v0.x += bb.x; v0.y += bb.y;
                v1.x += bb.x; v1.y += bb.y;
            }
            if (EPI == 1) {
                const float2 q0 = *(const float2*)(res + (size_t)r0 * N + n);
                const float2 q1 = *(const float2*)(res + (size_t)r1 * N + n);
                v0.x += q0.x; v0.y += q0.y;
                v1.x += q1.x; v1.y += q1.y;
            }
            if (EPI == 2) {
                v0.x = 0.5f * v0.x * (1.0f + erff(v0.x * 0.70710678f));
                v0.y = 0.5f * v0.y * (1.0f + erff(v0.y * 0.70710678f));
                v1.x = 0.5f * v1.x * (1.0f + erff(v1.x * 0.70710678f));
                v1.y = 0.5f * v1.y * (1.0f + erff(v1.y * 0.70710678f));
            }
            *(float2*)(C + (size_t)r0 * N + n) = v0;
            *(float2*)(C + (size_t)r1 * N + n) = v1;
        }
    }
}

/* ------------------------------------------------------------------ */
/* Tensor-core flash attention (TF32 mma).                             */
/* Block: 128 queries x one (b,h). 8 warps, each owns 16 query rows.   */
/* Q held as mma A-fragments in registers; K/V tiles (64 keys) in smem */
/* stride 72 (conflict-free B-frag LDS); P routed via smem stride 136. */
/* ------------------------------------------------------------------ */
#define KSTR 72
#define PSTR 136
/* dyn smem words: Ps 64*136 + Ks 64*72 + Vs 64*72 + mv 64 */
#define ATT_SMEM_WORDS (64*PSTR + 2*64*KSTR + 64)

__global__ void __launch_bounds__(256) attn_mma_kernel(
    const float* __restrict__ qkv, const int* __restrict__ mask,
    float* __restrict__ y)
{
    extern __shared__ uint32_t smw[];
    uint32_t* Ps = smw;                       /* [key][query] */
    uint32_t* Ks = smw + 64 * PSTR;           /* [key][d]     */
    uint32_t* Vs = Ks + 64 * KSTR;            /* [key][d]     */
    float*    mv = (float*)(Vs + 64 * KSTR);  /* [key]        */

    const int t    = threadIdx.x;
    const int lane = t & 31;
    const int grp  = lane >> 2;
    const int qid  = lane & 3;
    const int warp = t >> 5;
    const int mq   = warp << 4;               /* warp's query base (0..112) */

    const int b  = blockIdx.y / NH;
    const int h  = blockIdx.y - b * NH;
    const int q0 = blockIdx.x << 7;

    /* Q fragments in registers: rows mq+grp, mq+grp+8; cols 8ks+qid(+4) */
    uint32_t Qf[8][4];
    {
        const float* qp0 = qkv + (size_t)(b * SEQ + q0 + mq + grp) * QKV3 + h * HD;
        const float* qp1 = qp0 + (size_t)8 * QKV3;
#pragma unroll
        for (int ks = 0; ks < 8; ks++) {
            const int d = (ks << 3) + qid;
            Qf[ks][0] = f2tf32(qp0[d]     * ATT_SCALE);
            Qf[ks][1] = f2tf32(qp1[d]     * ATT_SCALE);
            Qf[ks][2] = f2tf32(qp0[d + 4] * ATT_SCALE);
            Qf[ks][3] = f2tf32(qp1[d + 4] * ATT_SCALE);
        }
    }

    float Oa[8][4];
#pragma unroll
    for (int nt = 0; nt < 8; nt++)
#pragma unroll
        for (int r = 0; r < 4; r++) Oa[nt][r] = 0.f;
    float m0 = -1e30f, m1 = -1e30f, l0 = 0.f, l1 = 0.f;

    for (int kt = 0; kt < SEQ; kt += 64) {
        __syncthreads();   /* previous tile's PV reads done before overwrite */
        {
            const int kr = t >> 2;            /* key row 0..63   */
            const int dq = (t & 3) << 4;      /* 0,16,32,48      */
            const float* kp = qkv + (size_t)(b * SEQ + kt + kr) * QKV3
                                  + DIM + h * HD + dq;
            const float* vp = kp + DIM;
#pragma unroll
            for (int i = 0; i < 16; i += 4) {
                float4 k4 = *(const float4*)(kp + i);
                float4 v4 = *(const float4*)(vp + i);
                Ks[kr * KSTR + dq + i + 0] = f2tf32(k4.x);
                Ks[kr * KSTR + dq + i + 1] = f2tf32(k4.y);
                Ks[kr * KSTR + dq + i + 2] = f2tf32(k4.z);
                Ks[kr * KSTR + dq + i + 3] = f2tf32(k4.w);
                Vs[kr * KSTR + dq + i + 0] = f2tf32(v4.x);
                Vs[kr * KSTR + dq + i + 1] = f2tf32(v4.y);
                Vs[kr * KSTR + dq + i + 2] = f2tf32(v4.z);
                Vs[kr * KSTR + dq + i + 3] = f2tf32(v4.w);
            }
            if (t < 64) mv[t] = mask[b * SEQ + kt + t] ? -1e30f : 0.f;
        }
        __syncthreads();

        /* S = Q K^T for this warp's 16 rows x 64 keys */
        float Sa[8][4];
#pragma unroll
        for (int nt = 0; nt < 8; nt++)
#pragma unroll
            for (int r = 0; r < 4; r++) Sa[nt][r] = 0.f;
#pragma unroll
        for (int ks = 0; ks < 8; ks++) {
            const int kk = ks << 3;
#pragma unroll
            for (int nt = 0; nt < 8; nt++) {
                uint32_t b0 = Ks[(nt * 8 + grp) * KSTR + kk + qid];
                uint32_t b1 = Ks[(nt * 8 + grp) * KSTR + kk + qid + 4];
                mma_tf32(Sa[nt], Qf[ks][0], Qf[ks][1], Qf[ks][2], Qf[ks][3],
                         b0, b1);
            }
        }

        /* mask + row max */
        float mx0 = -1e30f, mx1 = -1e30f;
#pragma unroll
        for (int nt = 0; nt < 8; nt++) {
            const float a0 = mv[nt * 8 + 2 * qid];
            const float a1 = mv[nt * 8 + 2 * qid + 1];
            Sa[nt][0] += a0; Sa[nt][1] += a1;
            Sa[nt][2] += a0; Sa[nt][3] += a1;
            mx0 = fmaxf(mx0, fmaxf(Sa[nt][0], Sa[nt][1]));
            mx1 = fmaxf(mx1, fmaxf(Sa[nt][2], Sa[nt][3]));
        }
        mx0 = fmaxf(mx0, __shfl_xor_sync(0xffffffffu, mx0, 1));
        mx0 = fmaxf(mx0, __shfl_xor_sync(0xffffffffu, mx0, 2));
        mx1 = fmaxf(mx1, __shfl_xor_sync(0xffffffffu, mx1, 1));
        mx1 = fmaxf(mx1, __shfl_xor_sync(0xffffffffu, mx1, 2));

        const float nm0 = fmaxf(m0, mx0);
        const float nm1 = fmaxf(m1, mx1);
        const float sc0 = __expf(m0 - nm0);
        const float sc1 = __expf(m1 - nm1);
        m0 = nm0; m1 = nm1;

        float s0 = 0.f, s1 = 0.f;
#pragma unroll
        for (int nt = 0; nt < 8; nt++) {
            const float p0 = __expf(Sa[nt][0] - nm0);
            const float p1 = __expf(Sa[nt][1] - nm0);
            const float p2 = __expf(Sa[nt][2] - nm1);
            const float p3 = __expf(Sa[nt][3] - nm1);
            s0 += p0 + p1; s1 += p2 + p3;
            const int kb = nt * 8 + 2 * qid;
            Ps[(kb    ) * PSTR + mq + grp]     = f2tf32(p0);
            Ps[(kb + 1) * PSTR + mq + grp]     = f2tf32(p1);
            Ps[(kb    ) * PSTR + mq + grp + 8] = f2tf32(p2);
            Ps[(kb + 1) * PSTR + mq + grp + 8] = f2tf32(p3);
        }
        s0 += __shfl_xor_sync(0xffffffffu, s0, 1);
        s0 += __shfl_xor_sync(0xffffffffu, s0, 2);
        s1 += __shfl_xor_sync(0xffffffffu, s1, 1);
        s1 += __shfl_xor_sync(0xffffffffu, s1, 2);
        l0 = l0 * sc0 + s0;
        l1 = l1 * sc1 + s1;

#pragma unroll
        for (int nt = 0; nt < 8; nt++) {
            Oa[nt][0] *= sc0; Oa[nt][1] *= sc0;
            Oa[nt][2] *= sc1; Oa[nt][3] *= sc1;
        }
        __syncwarp();

        /* O += P V  (k = keys) */
#pragma unroll
        for (int ks = 0; ks < 8; ks++) {
            const int kk = ks << 3;
            const uint32_t a0 = Ps[(kk + qid    ) * PSTR + mq + grp];
            const uint32_t a1 = Ps[(kk + qid    ) * PSTR + mq + grp + 8];
            const uint32_t a2 = Ps[(kk + qid + 4) * PSTR + mq + grp];
            const uint32_t a3 = Ps[(kk + qid + 4) * PSTR + mq + grp + 8];
#pragma unroll
            for (int nt = 0; nt < 8; nt++) {
                uint32_t b0 = Vs[(kk + qid    ) * KSTR + nt * 8 + grp];
                uint32_t b1 = Vs[(kk + qid + 4) * KSTR + nt * 8 + grp];
                mma_tf32(Oa[nt], a0, a1, a2, a3, b0, b1);
            }
        }
        __syncwarp();   /* Ps reads done before next tile overwrites */
    }

    const float i0 = 1.0f / l0;
    const float i1 = 1.0f / l1;
    float* yp0 = y + (size_t)(b * SEQ + q0 + mq + grp) * DIM + h * HD;
    float* yp1 = yp0 + (size_t)8 * DIM;
#pragma unroll
    for (int nt = 0; nt < 8; nt++) {
        const int d = nt * 8 + (qid << 1);
        float2 v0, v1;
        v0.x = Oa[nt][0] * i0; v0.y = Oa[nt][1] * i0;
        v1.x = Oa[nt][2] * i1; v1.y = Oa[nt][3] * i1;
        *(float2*)(yp0 + d) = v0;
        *(float2*)(yp1 + d) = v1;
    }
}

/* ------------------------------------------------------------------ */
/* launch                                                              */
/* ------------------------------------------------------------------ */
extern "C" void kernel_launch(void* const* d_in, const int* in_sizes, int n_in,
                              void* d_out, int out_size)
{
    (void)in_sizes; (void)n_in; (void)out_size;

    const float* x      = (const float*)d_in[0];
    const int*   mask   = (const int*)  d_in[1];
    const float* ln1_g  = (const float*)d_in[2];
    const float* ln1_b  = (const float*)d_in[3];
    const float* qkv_w  = (const float*)d_in[4];
    const float* proj_w = (const float*)d_in[5];
    const float* proj_b = (const float*)d_in[6];
    const float* ln2_g  = (const float*)d_in[7];
    const float* ln2_b  = (const float*)d_in[8];
    const float* fc1_w  = (const float*)d_in[9];
    const float* fc1_b  = (const float*)d_in[10];
    const float* fc2_w  = (const float*)d_in[11];
    const float* fc2_b  = (const float*)d_in[12];
    float* out = (float*)d_out;

    float *h, *qkv, *y, *x1, *h2;
    cudaGetSymbolAddress((void**)&h,   g_h);
    cudaGetSymbolAddress((void**)&qkv, g_qkv);
    cudaGetSymbolAddress((void**)&y,   g_y);
    cudaGetSymbolAddress((void**)&x1,  g_x1);
    cudaGetSymbolAddress((void**)&h2,  g_h2);

    /* idempotent, called every time (no static guards allowed) */
    cudaFuncSetAttribute(attn_mma_kernel,
                         cudaFuncAttributeMaxDynamicSharedMemorySize,
                         ATT_SMEM_WORDS * 4);

    /* 1. h = LN1(x) */
    ln_kernel<<<ROWS, 256>>>(x, ln1_g, ln1_b, h);

    /* 2. qkv = h @ qkv_w^T */
    gemm_mma<0><<<dim3(QKV3 / 128, ROWS / 128), 256>>>(
        h, qkv_w, nullptr, nullptr, qkv, ROWS, QKV3, DIM);

    /* 3. y = attention(qkv, mask) */
    attn_mma_kernel<<<dim3(SEQ / 128, BATCH * NH), 256, ATT_SMEM_WORDS * 4>>>(
        qkv, mask, y);

    /* 4. x1 = x + y @ proj_w^T + proj_b */
    gemm_mma<1><<<dim3(DIM / 128, ROWS / 128), 256>>>(
        y, proj_w, proj_b, x, x1, ROWS, DIM, DIM);

    /* 5. h = LN2(x1) */
    ln_kernel<<<ROWS, 256>>>(x1, ln2_g, ln2_b, h);

    /* 6. h2 = gelu(h @ fc1_w^T + fc1_b) */
    gemm_mma<2><<<dim3(HID / 128, ROWS / 128), 256>>>(
        h, fc1_w, fc1_b, nullptr, h2, ROWS, HID, DIM);

    /* 7. out = x1 + h2 @ fc2_w^T + fc2_b */
    gemm_mma<1><<<dim3(DIM / 128, ROWS / 128), 256>>>(
        h2, fc2_w, fc2_b, x1, out, ROWS, DIM, HID);
}

// round 12
// speedup vs baseline: 3.0517x; 1.0093x over previous
#include <cuda_runtime.h>
#include <math.h>
#include <stdint.h>

#define DIM   768
#define QKV3  2304
#define HID   3072
#define NH    12
#define HD    64
#define SEQ   2048
#define BATCH 2
#define ROWS  (BATCH*SEQ)        /* 4096 */
#define LNEPS 1e-5f
#define ATT_SCALE 0.125f         /* 64^-0.5 */

/* ------------------------------------------------------------------ */
/* scratch (device globals; no allocation allowed)                     */
/* ------------------------------------------------------------------ */
__device__ float  g_qkv [ROWS * QKV3];
__device__ float  g_y   [ROWS * DIM];
__device__ float  g_x1  [ROWS * DIM];
__device__ float  g_h2  [ROWS * HID];
__device__ float2 g_stat[ROWS];          /* per-row (mean, rstd) */

__device__ __forceinline__ uint32_t f2tf32(float x) {
    uint32_t r;
    asm("cvt.rna.tf32.f32 %0, %1;" : "=r"(r) : "f"(x));
    return r;
}

__device__ __forceinline__ void mma_tf32(float* c,
    uint32_t a0, uint32_t a1, uint32_t a2, uint32_t a3,
    uint32_t b0, uint32_t b1)
{
    asm volatile(
        "mma.sync.aligned.m16n8k8.row.col.f32.tf32.tf32.f32 "
        "{%0,%1,%2,%3}, {%4,%5,%6,%7}, {%8,%9}, {%0,%1,%2,%3};\n"
        : "+f"(c[0]), "+f"(c[1]), "+f"(c[2]), "+f"(c[3])
        : "r"(a0), "r"(a1), "r"(a2), "r"(a3), "r"(b0), "r"(b1));
}

/* ------------------------------------------------------------------ */
/* Row stats: one warp per row -> (mean, rstd).  768 = 32 lanes x 6x4. */
/* ------------------------------------------------------------------ */
__global__ void __launch_bounds__(256) row_stats(
    const float* __restrict__ x, float2* __restrict__ st)
{
    const int row  = blockIdx.x * 8 + (threadIdx.x >> 5);
    const int lane = threadIdx.x & 31;
    const float* xp = x + (size_t)row * DIM;

    float s = 0.f, ss = 0.f;
#pragma unroll
    for (int i = 0; i < 6; i++) {
        float4 v = *(const float4*)(xp + lane * 4 + i * 128);
        s  += (v.x + v.y) + (v.z + v.w);
        ss += (v.x * v.x + v.y * v.y) + (v.z * v.z + v.w * v.w);
    }
#pragma unroll
    for (int o = 16; o > 0; o >>= 1) {
        s  += __shfl_xor_sync(0xffffffffu, s,  o);
        ss += __shfl_xor_sync(0xffffffffu, ss, o);
    }
    if (lane == 0) {
        float mean = s * (1.0f / DIM);
        float var  = ss * (1.0f / DIM) - mean * mean;
        float2 r; r.x = mean; r.y = rsqrtf(var + LNEPS);
        st[row] = r;
    }
}

/* ------------------------------------------------------------------ */
/* TF32 tensor-core GEMM, fragment-pair smem layouts (LDS.64 frags).   */
/* C[m,n] = sum_k A'[m,k]*B[n,k]; A' = LN(A) when LNA=1.               */
/* 128x128 tile, 8 warps 2x4, warp 64x32, BK=16, double-buffered.      */
/* EPI: 0 plain | 1 +bias+residual | 2 +bias,GELU                      */
/* ------------------------------------------------------------------ */
#define ASTR 136   /* >=128, ==8 mod 32 */
#define BSTR 264   /* >=256, ==8 mod 32 */

__device__ __forceinline__ float4 ln4(float4 v, float mean, float rstd,
                                      float4 g, float4 b)
{
    float4 r;
    r.x = (v.x - mean) * rstd * g.x + b.x;
    r.y = (v.y - mean) * rstd * g.y + b.y;
    r.z = (v.z - mean) * rstd * g.z + b.z;
    r.w = (v.w - mean) * rstd * g.w + b.w;
    return r;
}

template <int EPI, int LNA>
__global__ void __launch_bounds__(256) gemm_mma(
    const float* __restrict__ A, const float* __restrict__ B,
    const float* __restrict__ bias, const float* __restrict__ res,
    float* __restrict__ C, const float2* __restrict__ stats,
    const float* __restrict__ lng, const float* __restrict__ lnb,
    int M, int N, int K)
{
    __shared__ uint32_t As2[2][16][ASTR];   /* [k][pos(m)]  pair (m,m+8) adjacent */
    __shared__ uint32_t Bs2[2][8][BSTR];    /* [r(k)][n*2+kbit2] pair (k,k+4) adj */

    const int t    = threadIdx.x;
    const int lane = t & 31;
    const int grp  = lane >> 2;
    const int qid  = lane & 3;
    const int warp = t >> 5;
    const int wm   = warp >> 2;
    const int wn   = warp & 3;

    const int m0 = blockIdx.y << 7;
    const int n0 = blockIdx.x << 7;

    const int lr = t >> 2;            /* 0..63  */
    const int lk = (t & 3) << 2;      /* 0,4,8,12 */
    const float* Ap0 = A + (size_t)(m0 + lr) * K + lk;
    const float* Ap1 = A + (size_t)(m0 + lr + 64) * K + lk;
    const float* Bp0 = B + (size_t)(n0 + lr) * K + lk;
    const float* Bp1 = B + (size_t)(n0 + lr + 64) * K + lk;

    /* writer positions */
    const int posA0 = ((lr >> 4) << 4) + ((lr & 7) << 1) + ((lr >> 3) & 1);
    const int posA1 = posA0 + 64;                 /* row lr+64 */
    const int brow  = (lk & 8) >> 1;              /* 0 or 4    */
    const int bbit  = (lk >> 2) & 1;              /* k bit2    */
    const int posB0 = (lr << 1) + bbit;
    const int posB1 = posB0 + 128;                /* row lr+64 */

    float2 st0, st1;
    if (LNA) {
        st0 = stats[m0 + lr];
        st1 = stats[m0 + lr + 64];
    }

    float acc[4][4][4];
#pragma unroll
    for (int i = 0; i < 4; i++)
#pragma unroll
        for (int j = 0; j < 4; j++)
#pragma unroll
            for (int r = 0; r < 4; r++) acc[i][j][r] = 0.f;

    float4 pa0 = *(const float4*)Ap0;
    float4 pa1 = *(const float4*)Ap1;
    float4 pb0 = *(const float4*)Bp0;
    float4 pb1 = *(const float4*)Bp1;
    float4 g4, b4;
    if (LNA) { g4 = *(const float4*)(lng + lk); b4 = *(const float4*)(lnb + lk); }

    int buf = 0;
    {
        float4 wa0 = pa0, wa1 = pa1;
        if (LNA) {
            wa0 = ln4(wa0, st0.x, st0.y, g4, b4);
            wa1 = ln4(wa1, st1.x, st1.y, g4, b4);
        }
        As2[0][lk + 0][posA0] = f2tf32(wa0.x);
        As2[0][lk + 1][posA0] = f2tf32(wa0.y);
        As2[0][lk + 2][posA0] = f2tf32(wa0.z);
        As2[0][lk + 3][posA0] = f2tf32(wa0.w);
        As2[0][lk + 0][posA1] = f2tf32(wa1.x);
        As2[0][lk + 1][posA1] = f2tf32(wa1.y);
        As2[0][lk + 2][posA1] = f2tf32(wa1.z);
        As2[0][lk + 3][posA1] = f2tf32(wa1.w);
        Bs2[0][brow + 0][posB0] = f2tf32(pb0.x);
        Bs2[0][brow + 1][posB0] = f2tf32(pb0.y);
        Bs2[0][brow + 2][posB0] = f2tf32(pb0.z);
        Bs2[0][brow + 3][posB0] = f2tf32(pb0.w);
        Bs2[0][brow + 0][posB1] = f2tf32(pb1.x);
        Bs2[0][brow + 1][posB1] = f2tf32(pb1.y);
        Bs2[0][brow + 2][posB1] = f2tf32(pb1.z);
        Bs2[0][brow + 3][posB1] = f2tf32(pb1.w);
    }
    __syncthreads();

    for (int k0 = 16; k0 <= K; k0 += 16) {
        const bool more = (k0 < K);
        if (more) {
            pa0 = *(const float4*)(Ap0 + k0);
            pa1 = *(const float4*)(Ap1 + k0);
            pb0 = *(const float4*)(Bp0 + k0);
            pb1 = *(const float4*)(Bp1 + k0);
            if (LNA) {
                g4 = *(const float4*)(lng + k0 + lk);
                b4 = *(const float4*)(lnb + k0 + lk);
            }
        }

#pragma unroll
        for (int ks = 0; ks < 2; ks++) {
            const int kk = ks << 3;
            uint2 a0[4], a1[4], bv[4];
#pragma unroll
            for (int mt = 0; mt < 4; mt++) {
                const int colA = wm * 64 + mt * 16 + (grp << 1);
                a0[mt] = *(const uint2*)&As2[buf][kk + qid][colA];
                a1[mt] = *(const uint2*)&As2[buf][kk + qid + 4][colA];
            }
#pragma unroll
            for (int nt = 0; nt < 4; nt++) {
                const int colB = (wn * 32 + nt * 8 + grp) << 1;
                bv[nt] = *(const uint2*)&Bs2[buf][qid + (kk >> 1)][colB];
            }
#pragma unroll
            for (int mt = 0; mt < 4; mt++)
#pragma unroll
                for (int nt = 0; nt < 4; nt++)
                    mma_tf32(acc[mt][nt], a0[mt].x, a0[mt].y,
                             a1[mt].x, a1[mt].y, bv[nt].x, bv[nt].y);
        }

        if (!more) break;
        buf ^= 1;
        {
            float4 wa0 = pa0, wa1 = pa1;
            if (LNA) {
                wa0 = ln4(wa0, st0.x, st0.y, g4, b4);
                wa1 = ln4(wa1, st1.x, st1.y, g4, b4);
            }
            As2[buf][lk + 0][posA0] = f2tf32(wa0.x);
            As2[buf][lk + 1][posA0] = f2tf32(wa0.y);
            As2[buf][lk + 2][posA0] = f2tf32(wa0.z);
            As2[buf][lk + 3][posA0] = f2tf32(wa0.w);
            As2[buf][lk + 0][posA1] = f2tf32(wa1.x);
            As2[buf][lk + 1][posA1] = f2tf32(wa1.y);
            As2[buf][lk + 2][posA1] = f2tf32(wa1.z);
            As2[buf][lk + 3][posA1] = f2tf32(wa1.w);
            Bs2[buf][brow + 0][posB0] = f2tf32(pb0.x);
            Bs2[buf][brow + 1][posB0] = f2tf32(pb0.y);
            Bs2[buf][brow + 2][posB0] = f2tf32(pb0.z);
            Bs2[buf][brow + 3][posB0] = f2tf32(pb0.w);
            Bs2[buf][brow + 0][posB1] = f2tf32(pb1.x);
            Bs2[buf][brow + 1][posB1] = f2tf32(pb1.y);
            Bs2[buf][brow + 2][posB1] = f2tf32(pb1.z);
            Bs2[buf][brow + 3][posB1] = f2tf32(pb1.w);
        }
        __syncthreads();
    }

#pragma unroll
    for (int mt = 0; mt < 4; mt++) {
        const int r0 = m0 + wm * 64 + mt * 16 + grp;
        const int r1 = r0 + 8;
#pragma unroll
        for (int nt = 0; nt < 4; nt++) {
            const int n = n0 + wn * 32 + nt * 8 + (qid << 1);
            float2 v0, v1;
            v0.x = acc[mt][nt][0]; v0.y = acc[mt][nt][1];
            v1.x = acc[mt][nt][2]; v1.y = acc[mt][nt][3];
            if (EPI >= 1) {
                const float2 bb = *(const float2*)(bias + n);
                v0.x += bb.x; v0.y += bb.y;
                v1.x += bb.x; v1.y += bb.y;
            }
            if (EPI == 1) {
                const float2 q0 = *(const float2*)(res + (size_t)r0 * N + n);
                const float2 q1 = *(const float2*)(res + (size_t)r1 * N + n);
                v0.x += q0.x; v0.y += q0.y;
                v1.x += q1.x; v1.y += q1.y;
            }
            if (EPI == 2) {
                v0.x = 0.5f * v0.x * (1.0f + erff(v0.x * 0.70710678f));
                v0.y = 0.5f * v0.y * (1.0f + erff(v0.y * 0.70710678f));
                v1.x = 0.5f * v1.x * (1.0f + erff(v1.x * 0.70710678f));
                v1.y = 0.5f * v1.y * (1.0f + erff(v1.y * 0.70710678f));
            }
            *(float2*)(C + (size_t)r0 * N + n) = v0;
            *(float2*)(C + (size_t)r1 * N + n) = v1;
        }
    }
}

/* ------------------------------------------------------------------ */
/* Tensor-core flash attention (TF32 mma) — unchanged from R11 passer. */
/* ------------------------------------------------------------------ */
#define KSTR 72
#define PSTR 136
#define ATT_SMEM_WORDS (64*PSTR + 2*64*KSTR + 64)

__global__ void __launch_bounds__(256) attn_mma_kernel(
    const float* __restrict__ qkv, const int* __restrict__ mask,
    float* __restrict__ y)
{
    extern __shared__ uint32_t smw[];
    uint32_t* Ps = smw;
    uint32_t* Ks = smw + 64 * PSTR;
    uint32_t* Vs = Ks + 64 * KSTR;
    float*    mv = (float*)(Vs + 64 * KSTR);

    const int t    = threadIdx.x;
    const int lane = t & 31;
    const int grp  = lane >> 2;
    const int qid  = lane & 3;
    const int warp = t >> 5;
    const int mq   = warp << 4;

    const int b  = blockIdx.y / NH;
    const int h  = blockIdx.y - b * NH;
    const int q0 = blockIdx.x << 7;

    uint32_t Qf[8][4];
    {
        const float* qp0 = qkv + (size_t)(b * SEQ + q0 + mq + grp) * QKV3 + h * HD;
        const float* qp1 = qp0 + (size_t)8 * QKV3;
#pragma unroll
        for (int ks = 0; ks < 8; ks++) {
            const int d = (ks << 3) + qid;
            Qf[ks][0] = f2tf32(qp0[d]     * ATT_SCALE);
            Qf[ks][1] = f2tf32(qp1[d]     * ATT_SCALE);
            Qf[ks][2] = f2tf32(qp0[d + 4] * ATT_SCALE);
            Qf[ks][3] = f2tf32(qp1[d + 4] * ATT_SCALE);
        }
    }

    float Oa[8][4];
#pragma unroll
    for (int nt = 0; nt < 8; nt++)
#pragma unroll
        for (int r = 0; r < 4; r++) Oa[nt][r] = 0.f;
    float m0 = -1e30f, m1 = -1e30f, l0 = 0.f, l1 = 0.f;

    for (int kt = 0; kt < SEQ; kt += 64) {
        __syncthreads();
        {
            const int kr = t >> 2;
            const int dq = (t & 3) << 4;
            const float* kp = qkv + (size_t)(b * SEQ + kt + kr) * QKV3
                                  + DIM + h * HD + dq;
            const float* vp = kp + DIM;
#pragma unroll
            for (int i = 0; i < 16; i += 4) {
                float4 k4 = *(const float4*)(kp + i);
                float4 v4 = *(const float4*)(vp + i);
                Ks[kr * KSTR + dq + i + 0] = f2tf32(k4.x);
                Ks[kr * KSTR + dq + i + 1] = f2tf32(k4.y);
                Ks[kr * KSTR + dq + i + 2] = f2tf32(k4.z);
                Ks[kr * KSTR + dq + i + 3] = f2tf32(k4.w);
                Vs[kr * KSTR + dq + i + 0] = f2tf32(v4.x);
                Vs[kr * KSTR + dq + i + 1] = f2tf32(v4.y);
                Vs[kr * KSTR + dq + i + 2] = f2tf32(v4.z);
                Vs[kr * KSTR + dq + i + 3] = f2tf32(v4.w);
            }
            if (t < 64) mv[t] = mask[b * SEQ + kt + t] ? -1e30f : 0.f;
        }
        __syncthreads();

        float Sa[8][4];
#pragma unroll
        for (int nt = 0; nt < 8; nt++)
#pragma unroll
            for (int r = 0; r < 4; r++) Sa[nt][r] = 0.f;
#pragma unroll
        for (int ks = 0; ks < 8; ks++) {
            const int kk = ks << 3;
#pragma unroll
            for (int nt = 0; nt < 8; nt++) {
                uint32_t b0 = Ks[(nt * 8 + grp) * KSTR + kk + qid];
                uint32_t b1 = Ks[(nt * 8 + grp) * KSTR + kk + qid + 4];
                mma_tf32(Sa[nt], Qf[ks][0], Qf[ks][1], Qf[ks][2], Qf[ks][3],
                         b0, b1);
            }
        }

        float mx0 = -1e30f, mx1 = -1e30f;
#pragma unroll
        for (int nt = 0; nt < 8; nt++) {
            const float a0 = mv[nt * 8 + 2 * qid];
            const float a1 = mv[nt * 8 + 2 * qid + 1];
            Sa[nt][0] += a0; Sa[nt][1] += a1;
            Sa[nt][2] += a0; Sa[nt][3] += a1;
            mx0 = fmaxf(mx0, fmaxf(Sa[nt][0], Sa[nt][1]));
            mx1 = fmaxf(mx1, fmaxf(Sa[nt][2], Sa[nt][3]));
        }
        mx0 = fmaxf(mx0, __shfl_xor_sync(0xffffffffu, mx0, 1));
        mx0 = fmaxf(mx0, __shfl_xor_sync(0xffffffffu, mx0, 2));
        mx1 = fmaxf(mx1, __shfl_xor_sync(0xffffffffu, mx1, 1));
        mx1 = fmaxf(mx1, __shfl_xor_sync(0xffffffffu, mx1, 2));

        const float nm0 = fmaxf(m0, mx0);
        const float nm1 = fmaxf(m1, mx1);
        const float sc0 = __expf(m0 - nm0);
        const float sc1 = __expf(m1 - nm1);
        m0 = nm0; m1 = nm1;

        float s0 = 0.f, s1 = 0.f;
#pragma unroll
        for (int nt = 0; nt < 8; nt++) {
            const float p0 = __expf(Sa[nt][0] - nm0);
            const float p1 = __expf(Sa[nt][1] - nm0);
            const float p2 = __expf(Sa[nt][2] - nm1);
            const float p3 = __expf(Sa[nt][3] - nm1);
            s0 += p0 + p1; s1 += p2 + p3;
            const int kb = nt * 8 + 2 * qid;
            Ps[(kb    ) * PSTR + mq + grp]     = f2tf32(p0);
            Ps[(kb + 1) * PSTR + mq + grp]     = f2tf32(p1);
            Ps[(kb    ) * PSTR + mq + grp + 8] = f2tf32(p2);
            Ps[(kb + 1) * PSTR + mq + grp + 8] = f2tf32(p3);
        }
        s0 += __shfl_xor_sync(0xffffffffu, s0, 1);
        s0 += __shfl_xor_sync(0xffffffffu, s0, 2);
        s1 += __shfl_xor_sync(0xffffffffu, s1, 1);
        s1 += __shfl_xor_sync(0xffffffffu, s1, 2);
        l0 = l0 * sc0 + s0;
        l1 = l1 * sc1 + s1;

#pragma unroll
        for (int nt = 0; nt < 8; nt++) {
            Oa[nt][0] *= sc0; Oa[nt][1] *= sc0;
            Oa[nt][2] *= sc1; Oa[nt][3] *= sc1;
        }
        __syncwarp();

#pragma unroll
        for (int ks = 0; ks < 8; ks++) {
            const int kk = ks << 3;
            const uint32_t a0 = Ps[(kk + qid    ) * PSTR + mq + grp];
            const uint32_t a1 = Ps[(kk + qid    ) * PSTR + mq + grp + 8];
            const uint32_t a2 = Ps[(kk + qid + 4) * PSTR + mq + grp];
            const uint32_t a3 = Ps[(kk + qid + 4) * PSTR + mq + grp + 8];
#pragma unroll
            for (int nt = 0; nt < 8; nt++) {
                uint32_t b0 = Vs[(kk + qid    ) * KSTR + nt * 8 + grp];
                uint32_t b1 = Vs[(kk + qid + 4) * KSTR + nt * 8 + grp];
                mma_tf32(Oa[nt], a0, a1, a2, a3, b0, b1);
            }
        }
        __syncwarp();
    }

    const float i0 = 1.0f / l0;
    const float i1 = 1.0f / l1;
    float* yp0 = y + (size_t)(b * SEQ + q0 + mq + grp) * DIM + h * HD;
    float* yp1 = yp0 + (size_t)8 * DIM;
#pragma unroll
    for (int nt = 0; nt < 8; nt++) {
        const int d = nt * 8 + (qid << 1);
        float2 v0, v1;
        v0.x = Oa[nt][0] * i0; v0.y = Oa[nt][1] * i0;
        v1.x = Oa[nt][2] * i1; v1.y = Oa[nt][3] * i1;
        *(float2*)(yp0 + d) = v0;
        *(float2*)(yp1 + d) = v1;
    }
}

/* ------------------------------------------------------------------ */
/* launch                                                              */
/* ------------------------------------------------------------------ */
extern "C" void kernel_launch(void* const* d_in, const int* in_sizes, int n_in,
                              void* d_out, int out_size)
{
    (void)in_sizes; (void)n_in; (void)out_size;

    const float* x      = (const float*)d_in[0];
    const int*   mask   = (const int*)  d_in[1];
    const float* ln1_g  = (const float*)d_in[2];
    const float* ln1_b  = (const float*)d_in[3];
    const float* qkv_w  = (const float*)d_in[4];
    const float* proj_w = (const float*)d_in[5];
    const float* proj_b = (const float*)d_in[6];
    const float* ln2_g  = (const float*)d_in[7];
    const float* ln2_b  = (const float*)d_in[8];
    const float* fc1_w  = (const float*)d_in[9];
    const float* fc1_b  = (const float*)d_in[10];
    const float* fc2_w  = (const float*)d_in[11];
    const float* fc2_b  = (const float*)d_in[12];
    float* out = (float*)d_out;

    float *qkv, *y, *x1, *h2;
    float2* st;
    cudaGetSymbolAddress((void**)&qkv, g_qkv);
    cudaGetSymbolAddress((void**)&y,   g_y);
    cudaGetSymbolAddress((void**)&x1,  g_x1);
    cudaGetSymbolAddress((void**)&h2,  g_h2);
    cudaGetSymbolAddress((void**)&st,  g_stat);

    /* idempotent, every call (no static guards allowed) */
    cudaFuncSetAttribute(attn_mma_kernel,
                         cudaFuncAttributeMaxDynamicSharedMemorySize,
                         ATT_SMEM_WORDS * 4);

    /* 1. LN1 stats */
    row_stats<<<ROWS / 8, 256>>>(x, st);

    /* 2. qkv = LN1(x) @ qkv_w^T  (LN fused into A-path) */
    gemm_mma<0, 1><<<dim3(QKV3 / 128, ROWS / 128), 256>>>(
        x, qkv_w, nullptr, nullptr, qkv, st, ln1_g, ln1_b, ROWS, QKV3, DIM);

    /* 3. y = attention(qkv, mask) */
    attn_mma_kernel<<<dim3(SEQ / 128, BATCH * NH), 256, ATT_SMEM_WORDS * 4>>>(
        qkv, mask, y);

    /* 4. x1 = x + y @ proj_w^T + proj_b */
    gemm_mma<1, 0><<<dim3(DIM / 128, ROWS / 128), 256>>>(
        y, proj_w, proj_b, x, x1, nullptr, nullptr, nullptr, ROWS, DIM, DIM);

    /* 5. LN2 stats */
    row_stats<<<ROWS / 8, 256>>>(x1, st);

    /* 6. h2 = gelu(LN2(x1) @ fc1_w^T + fc1_b)  (LN fused) */
    gemm_mma<2, 1><<<dim3(HID / 128, ROWS / 128), 256>>>(
        x1, fc1_w, fc1_b, nullptr, h2, st, ln2_g, ln2_b, ROWS, HID, DIM);

    /* 7. out = x1 + h2 @ fc2_w^T + fc2_b */
    gemm_mma<1, 0><<<dim3(DIM / 128, ROWS / 128), 256>>>(
        h2, fc2_w, fc2_b, x1, out, nullptr, nullptr, nullptr, ROWS, DIM, HID);
}

// round 13
// speedup vs baseline: 3.1330x; 1.0266x over previous
#include <cuda_runtime.h>
#include <math.h>
#include <stdint.h>

#define DIM   768
#define QKV3  2304
#define HID   3072
#define NH    12
#define HD    64
#define SEQ   2048
#define BATCH 2
#define ROWS  (BATCH*SEQ)        /* 4096 */
#define LNEPS 1e-5f
#define ATT_SCALE 0.125f         /* 64^-0.5 */

/* ------------------------------------------------------------------ */
/* scratch (device globals; no allocation allowed)                     */
/* ------------------------------------------------------------------ */
__device__ float  g_qkv [ROWS * QKV3];
__device__ float  g_y   [ROWS * DIM];
__device__ float  g_x1  [ROWS * DIM];
__device__ float  g_h2  [ROWS * HID];
__device__ float2 g_stat[ROWS];          /* per-row (mean, rstd)      */
__device__ float  g_w1  [QKV3 * DIM];    /* qkv_w * ln1_g             */
__device__ float  g_w2  [HID * DIM];     /* fc1_w * ln2_g             */
__device__ float  g_c1a [QKV3], g_c2a[QKV3];
__device__ float  g_c1b [HID],  g_c2b[HID];

__device__ __forceinline__ uint32_t f2tf32(float x) {
    uint32_t r;
    asm("cvt.rna.tf32.f32 %0, %1;" : "=r"(r) : "f"(x));
    return r;
}

__device__ __forceinline__ void mma_tf32(float* c,
    uint32_t a0, uint32_t a1, uint32_t a2, uint32_t a3,
    uint32_t b0, uint32_t b1)
{
    asm volatile(
        "mma.sync.aligned.m16n8k8.row.col.f32.tf32.tf32.f32 "
        "{%0,%1,%2,%3}, {%4,%5,%6,%7}, {%8,%9}, {%0,%1,%2,%3};\n"
        : "+f"(c[0]), "+f"(c[1]), "+f"(c[2]), "+f"(c[3])
        : "r"(a0), "r"(a1), "r"(a2), "r"(a3), "r"(b0), "r"(b1));
}

/* ------------------------------------------------------------------ */
/* Row stats: one warp per row -> (mean, rstd)                         */
/* ------------------------------------------------------------------ */
__global__ void __launch_bounds__(256) row_stats(
    const float* __restrict__ x, float2* __restrict__ st)
{
    const int row  = blockIdx.x * 8 + (threadIdx.x >> 5);
    const int lane = threadIdx.x & 31;
    const float* xp = x + (size_t)row * DIM;

    float s = 0.f, ss = 0.f;
#pragma unroll
    for (int i = 0; i < 6; i++) {
        float4 v = *(const float4*)(xp + lane * 4 + i * 128);
        s  += (v.x + v.y) + (v.z + v.w);
        ss += (v.x * v.x + v.y * v.y) + (v.z * v.z + v.w * v.w);
    }
#pragma unroll
    for (int o = 16; o > 0; o >>= 1) {
        s  += __shfl_xor_sync(0xffffffffu, s,  o);
        ss += __shfl_xor_sync(0xffffffffu, ss, o);
    }
    if (lane == 0) {
        float mean = s * (1.0f / DIM);
        float var  = ss * (1.0f / DIM) - mean * mean;
        float2 r; r.x = mean; r.y = rsqrtf(var + LNEPS);
        st[row] = r;
    }
}

/* ------------------------------------------------------------------ */
/* Weight transform: W'[n,k]=w*g, c1[n]=sum W', c2[n]=sum w*b.         */
/* One warp per n-row, K = DIM = 768.                                  */
/* ------------------------------------------------------------------ */
__global__ void __launch_bounds__(256) prep_w(
    const float* __restrict__ w, const float* __restrict__ g,
    const float* __restrict__ b, float* __restrict__ wp,
    float* __restrict__ c1, float* __restrict__ c2)
{
    const int row  = blockIdx.x * 8 + (threadIdx.x >> 5);
    const int lane = threadIdx.x & 31;
    const float* wr = w + (size_t)row * DIM;
    float* wo = wp + (size_t)row * DIM;

    float s1 = 0.f, s2 = 0.f;
#pragma unroll
    for (int i = 0; i < 6; i++) {
        const int c = lane * 4 + i * 128;
        float4 w4 = *(const float4*)(wr + c);
        float4 g4 = *(const float4*)(g + c);
        float4 b4 = *(const float4*)(b + c);
        float4 o;
        o.x = w4.x * g4.x; o.y = w4.y * g4.y;
        o.z = w4.z * g4.z; o.w = w4.w * g4.w;
        s1 += (o.x + o.y) + (o.z + o.w);
        s2 += (w4.x * b4.x + w4.y * b4.y) + (w4.z * b4.z + w4.w * b4.w);
        *(float4*)(wo + c) = o;
    }
#pragma unroll
    for (int o = 16; o > 0; o >>= 1) {
        s1 += __shfl_xor_sync(0xffffffffu, s1, o);
        s2 += __shfl_xor_sync(0xffffffffu, s2, o);
    }
    if (lane == 0) { c1[row] = s1; c2[row] = s2; }
}

/* ------------------------------------------------------------------ */
/* Pure TF32 GEMM, fragment-pair layouts, BM=128, BN in {128,64}.      */
/* C[m,n] = sum_k A[m,k]*B[n,k].                                       */
/* EPI 0: v = r*acc - r*mean*c1[n] + c2[n]            (qkv, LN exact)  */
/* EPI 1: v = acc + bias[n] + res[m,n]                (proj/fc2)       */
/* EPI 2: v = gelu(r*acc - r*mean*c1[n] + c2[n] + bias[n])  (fc1)      */
/* ------------------------------------------------------------------ */
template <int EPI, int BN>
__global__ void __launch_bounds__(256) gemm_mma(
    const float* __restrict__ A, const float* __restrict__ B,
    const float* __restrict__ bias, const float* __restrict__ res,
    float* __restrict__ C, const float2* __restrict__ stats,
    const float* __restrict__ c1v, const float* __restrict__ c2v,
    int M, int N, int K)
{
    constexpr int BSTR_ = (BN == 128) ? 264 : 136;  /* ==8 mod 32 */
    constexpr int MT    = (BN == 128) ? 4 : 2;
    constexpr int WMS   = (BN == 128) ? 64 : 32;    /* warp m-extent */
    __shared__ uint32_t As2[2][16][136];
    __shared__ uint32_t Bs2[2][8][BSTR_];

    const int t    = threadIdx.x;
    const int lane = t & 31;
    const int grp  = lane >> 2;
    const int qid  = lane & 3;
    const int warp = t >> 5;
    const int wm   = (BN == 128) ? (warp >> 2) : (warp >> 1);
    const int wn   = (BN == 128) ? (warp & 3) : (warp & 1);

    const int m0 = blockIdx.y << 7;
    const int n0 = blockIdx.x * BN;

    const int lr = t >> 2;            /* 0..63  */
    const int lk = (t & 3) << 2;      /* 0,4,8,12 */
    const float* Ap0 = A + (size_t)(m0 + lr) * K + lk;
    const float* Ap1 = Ap0 + (size_t)64 * K;
    const float* Bp0 = B + (size_t)(n0 + lr) * K + lk;
    const float* Bp1 = Bp0 + (size_t)64 * K;    /* used only if BN==128 */

    const int posA0 = ((lr >> 4) << 4) + ((lr & 7) << 1) + ((lr >> 3) & 1);
    const int posA1 = posA0 + 64;
    const int brow  = (lk & 8) >> 1;
    const int bbit  = (lk >> 2) & 1;
    const int posB0 = (lr << 1) + bbit;
    const int posB1 = posB0 + 128;

    float acc[MT][4][4];
#pragma unroll
    for (int i = 0; i < MT; i++)
#pragma unroll
        for (int j = 0; j < 4; j++)
#pragma unroll
            for (int r = 0; r < 4; r++) acc[i][j][r] = 0.f;

    float4 pa0 = *(const float4*)Ap0;
    float4 pa1 = *(const float4*)Ap1;
    float4 pb0 = *(const float4*)Bp0;
    float4 pb1;
    if (BN == 128) pb1 = *(const float4*)Bp1;

    int buf = 0;
    {
        As2[0][lk + 0][posA0] = f2tf32(pa0.x);
        As2[0][lk + 1][posA0] = f2tf32(pa0.y);
        As2[0][lk + 2][posA0] = f2tf32(pa0.z);
        As2[0][lk + 3][posA0] = f2tf32(pa0.w);
        As2[0][lk + 0][posA1] = f2tf32(pa1.x);
        As2[0][lk + 1][posA1] = f2tf32(pa1.y);
        As2[0][lk + 2][posA1] = f2tf32(pa1.z);
        As2[0][lk + 3][posA1] = f2tf32(pa1.w);
        Bs2[0][brow + 0][posB0] = f2tf32(pb0.x);
        Bs2[0][brow + 1][posB0] = f2tf32(pb0.y);
        Bs2[0][brow + 2][posB0] = f2tf32(pb0.z);
        Bs2[0][brow + 3][posB0] = f2tf32(pb0.w);
        if (BN == 128) {
            Bs2[0][brow + 0][posB1] = f2tf32(pb1.x);
            Bs2[0][brow + 1][posB1] = f2tf32(pb1.y);
            Bs2[0][brow + 2][posB1] = f2tf32(pb1.z);
            Bs2[0][brow + 3][posB1] = f2tf32(pb1.w);
        }
    }
    __syncthreads();

    for (int k0 = 16; k0 <= K; k0 += 16) {
        const bool more = (k0 < K);
        if (more) {
            pa0 = *(const float4*)(Ap0 + k0);
            pa1 = *(const float4*)(Ap1 + k0);
            pb0 = *(const float4*)(Bp0 + k0);
            if (BN == 128) pb1 = *(const float4*)(Bp1 + k0);
        }

#pragma unroll
        for (int ks = 0; ks < 2; ks++) {
            const int kk = ks << 3;
            uint2 a0[MT], a1[MT], bv[4];
#pragma unroll
            for (int mt = 0; mt < MT; mt++) {
                const int colA = wm * WMS + mt * 16 + (grp << 1);
                a0[mt] = *(const uint2*)&As2[buf][kk + qid][colA];
                a1[mt] = *(const uint2*)&As2[buf][kk + qid + 4][colA];
            }
#pragma unroll
            for (int nt = 0; nt < 4; nt++) {
                const int colB = (wn * 32 + nt * 8 + grp) << 1;
                bv[nt] = *(const uint2*)&Bs2[buf][qid + (kk >> 1)][colB];
            }
#pragma unroll
            for (int mt = 0; mt < MT; mt++)
#pragma unroll
                for (int nt = 0; nt < 4; nt++)
                    mma_tf32(acc[mt][nt], a0[mt].x, a0[mt].y,
                             a1[mt].x, a1[mt].y, bv[nt].x, bv[nt].y);
        }

        if (!more) break;
        buf ^= 1;
        As2[buf][lk + 0][posA0] = f2tf32(pa0.x);
        As2[buf][lk + 1][posA0] = f2tf32(pa0.y);
        As2[buf][lk + 2][posA0] = f2tf32(pa0.z);
        As2[buf][lk + 3][posA0] = f2tf32(pa0.w);
        As2[buf][lk + 0][posA1] = f2tf32(pa1.x);
        As2[buf][lk + 1][posA1] = f2tf32(pa1.y);
        As2[buf][lk + 2][posA1] = f2tf32(pa1.z);
        As2[buf][lk + 3][posA1] = f2tf32(pa1.w);
        Bs2[buf][brow + 0][posB0] = f2tf32(pb0.x);
        Bs2[buf][brow + 1][posB0] = f2tf32(pb0.y);
        Bs2[buf][brow + 2][posB0] = f2tf32(pb0.z);
        Bs2[buf][brow + 3][posB0] = f2tf32(pb0.w);
        if (BN == 128) {
            Bs2[buf][brow + 0][posB1] = f2tf32(pb1.x);
            Bs2[buf][brow + 1][posB1] = f2tf32(pb1.y);
            Bs2[buf][brow + 2][posB1] = f2tf32(pb1.z);
            Bs2[buf][brow + 3][posB1] = f2tf32(pb1.w);
        }
        __syncthreads();
    }

#pragma unroll
    for (int mt = 0; mt < MT; mt++) {
        const int r0 = m0 + wm * WMS + mt * 16 + grp;
        const int r1 = r0 + 8;
        float rs0 = 0.f, rm0 = 0.f, rs1 = 0.f, rm1 = 0.f;
        if (EPI == 0 || EPI == 2) {
            const float2 s0 = stats[r0];
            const float2 s1 = stats[r1];
            rs0 = s0.y; rm0 = s0.y * s0.x;
            rs1 = s1.y; rm1 = s1.y * s1.x;
        }
#pragma unroll
        for (int nt = 0; nt < 4; nt++) {
            const int n = n0 + wn * 32 + nt * 8 + (qid << 1);
            float2 v0, v1;
            v0.x = acc[mt][nt][0]; v0.y = acc[mt][nt][1];
            v1.x = acc[mt][nt][2]; v1.y = acc[mt][nt][3];
            if (EPI == 0 || EPI == 2) {
                const float2 c1_ = *(const float2*)(c1v + n);
                const float2 c2_ = *(const float2*)(c2v + n);
                v0.x = rs0 * v0.x - rm0 * c1_.x + c2_.x;
                v0.y = rs0 * v0.y - rm0 * c1_.y + c2_.y;
                v1.x = rs1 * v1.x - rm1 * c1_.x + c2_.x;
                v1.y = rs1 * v1.y - rm1 * c1_.y + c2_.y;
            }
            if (EPI == 1 || EPI == 2) {
                const float2 bb = *(const float2*)(bias + n);
                v0.x += bb.x; v0.y += bb.y;
                v1.x += bb.x; v1.y += bb.y;
            }
            if (EPI == 1) {
                const float2 q0 = *(const float2*)(res + (size_t)r0 * N + n);
                const float2 q1 = *(const float2*)(res + (size_t)r1 * N + n);
                v0.x += q0.x; v0.y += q0.y;
                v1.x += q1.x; v1.y += q1.y;
            }
            if (EPI == 2) {
                v0.x = 0.5f * v0.x * (1.0f + erff(v0.x * 0.70710678f));
                v0.y = 0.5f * v0.y * (1.0f + erff(v0.y * 0.70710678f));
                v1.x = 0.5f * v1.x * (1.0f + erff(v1.x * 0.70710678f));
                v1.y = 0.5f * v1.y * (1.0f + erff(v1.y * 0.70710678f));
            }
            *(float2*)(C + (size_t)r0 * N + n) = v0;
            *(float2*)(C + (size_t)r1 * N + n) = v1;
        }
    }
}

/* ------------------------------------------------------------------ */
/* Tensor-core flash attention (TF32 mma).                             */
/* K/V stored raw f32 via STS.128 (tf32 truncation in mma); P raw bits.*/
/* ------------------------------------------------------------------ */
#define KSTR 72
#define PSTR 136
#define ATT_SMEM_WORDS (64*PSTR + 2*64*KSTR + 64)

__global__ void __launch_bounds__(256) attn_mma_kernel(
    const float* __restrict__ qkv, const int* __restrict__ mask,
    float* __restrict__ y)
{
    extern __shared__ uint32_t smw[];
    uint32_t* Ps  = smw;
    float*    Ksf = (float*)(smw + 64 * PSTR);
    float*    Vsf = Ksf + 64 * KSTR;
    float*    mv  = Vsf + 64 * KSTR;

    const int t    = threadIdx.x;
    const int lane = t & 31;
    const int grp  = lane >> 2;
    const int qid  = lane & 3;
    const int warp = t >> 5;
    const int mq   = warp << 4;

    const int b  = blockIdx.y / NH;
    const int h  = blockIdx.y - b * NH;
    const int q0 = blockIdx.x << 7;

    uint32_t Qf[8][4];
    {
        const float* qp0 = qkv + (size_t)(b * SEQ + q0 + mq + grp) * QKV3 + h * HD;
        const float* qp1 = qp0 + (size_t)8 * QKV3;
#pragma unroll
        for (int ks = 0; ks < 8; ks++) {
            const int d = (ks << 3) + qid;
            Qf[ks][0] = f2tf32(qp0[d]     * ATT_SCALE);
            Qf[ks][1] = f2tf32(qp1[d]     * ATT_SCALE);
            Qf[ks][2] = f2tf32(qp0[d + 4] * ATT_SCALE);
            Qf[ks][3] = f2tf32(qp1[d + 4] * ATT_SCALE);
        }
    }

    float Oa[8][4];
#pragma unroll
    for (int nt = 0; nt < 8; nt++)
#pragma unroll
        for (int r = 0; r < 4; r++) Oa[nt][r] = 0.f;
    float m0 = -1e30f, m1 = -1e30f, l0 = 0.f, l1 = 0.f;

    for (int kt = 0; kt < SEQ; kt += 64) {
        __syncthreads();
        {
            const int kr = t >> 2;
            const int dq = (t & 3) << 4;
            const float* kp = qkv + (size_t)(b * SEQ + kt + kr) * QKV3
                                  + DIM + h * HD + dq;
            const float* vp = kp + DIM;
#pragma unroll
            for (int i = 0; i < 16; i += 4) {
                *(float4*)&Ksf[kr * KSTR + dq + i] = *(const float4*)(kp + i);
                *(float4*)&Vsf[kr * KSTR + dq + i] = *(const float4*)(vp + i);
            }
            if (t < 64) mv[t] = mask[b * SEQ + kt + t] ? -1e30f : 0.f;
        }
        __syncthreads();

        float Sa[8][4];
#pragma unroll
        for (int nt = 0; nt < 8; nt++)
#pragma unroll
            for (int r = 0; r < 4; r++) Sa[nt][r] = 0.f;
#pragma unroll
        for (int ks = 0; ks < 8; ks++) {
            const int kk = ks << 3;
#pragma unroll
            for (int nt = 0; nt < 8; nt++) {
                uint32_t b0 = __float_as_uint(Ksf[(nt * 8 + grp) * KSTR + kk + qid]);
                uint32_t b1 = __float_as_uint(Ksf[(nt * 8 + grp) * KSTR + kk + qid + 4]);
                mma_tf32(Sa[nt], Qf[ks][0], Qf[ks][1], Qf[ks][2], Qf[ks][3],
                         b0, b1);
            }
        }

        float mx0 = -1e30f, mx1 = -1e30f;
#pragma unroll
        for (int nt = 0; nt < 8; nt++) {
            const float a0 = mv[nt * 8 + 2 * qid];
            const float a1 = mv[nt * 8 + 2 * qid + 1];
            Sa[nt][0] += a0; Sa[nt][1] += a1;
            Sa[nt][2] += a0; Sa[nt][3] += a1;
            mx0 = fmaxf(mx0, fmaxf(Sa[nt][0], Sa[nt][1]));
            mx1 = fmaxf(mx1, fmaxf(Sa[nt][2], Sa[nt][3]));
        }
        mx0 = fmaxf(mx0, __shfl_xor_sync(0xffffffffu, mx0, 1));
        mx0 = fmaxf(mx0, __shfl_xor_sync(0xffffffffu, mx0, 2));
        mx1 = fmaxf(mx1, __shfl_xor_sync(0xffffffffu, mx1, 1));
        mx1 = fmaxf(mx1, __shfl_xor_sync(0xffffffffu, mx1, 2));

        const float nm0 = fmaxf(m0, mx0);
        const float nm1 = fmaxf(m1, mx1);
        const float sc0 = __expf(m0 - nm0);
        const float sc1 = __expf(m1 - nm1);
        m0 = nm0; m1 = nm1;

        float s0 = 0.f, s1 = 0.f;
#pragma unroll
        for (int nt = 0; nt < 8; nt++) {
            const float p0 = __expf(Sa[nt][0] - nm0);
            const float p1 = __expf(Sa[nt][1] - nm0);
            const float p2 = __expf(Sa[nt][2] - nm1);
            const float p3 = __expf(Sa[nt][3] - nm1);
            s0 += p0 + p1; s1 += p2 + p3;
            const int kb = nt * 8 + 2 * qid;
            Ps[(kb    ) * PSTR + mq + grp]     = __float_as_uint(p0);
            Ps[(kb + 1) * PSTR + mq + grp]     = __float_as_uint(p1);
            Ps[(kb    ) * PSTR + mq + grp + 8] = __float_as_uint(p2);
            Ps[(kb + 1) * PSTR + mq + grp + 8] = __float_as_uint(p3);
        }
        s0 += __shfl_xor_sync(0xffffffffu, s0, 1);
        s0 += __shfl_xor_sync(0xffffffffu, s0, 2);
        s1 += __shfl_xor_sync(0xffffffffu, s1, 1);
        s1 += __shfl_xor_sync(0xffffffffu, s1, 2);
        l0 = l0 * sc0 + s0;
        l1 = l1 * sc1 + s1;

#pragma unroll
        for (int nt = 0; nt < 8; nt++) {
            Oa[nt][0] *= sc0; Oa[nt][1] *= sc0;
            Oa[nt][2] *= sc1; Oa[nt][3] *= sc1;
        }
        __syncwarp();

#pragma unroll
        for (int ks = 0; ks < 8; ks++) {
            const int kk = ks << 3;
            const uint32_t a0 = Ps[(kk + qid    ) * PSTR + mq + grp];
            const uint32_t a1 = Ps[(kk + qid    ) * PSTR + mq + grp + 8];
            const uint32_t a2 = Ps[(kk + qid + 4) * PSTR + mq + grp];
            const uint32_t a3 = Ps[(kk + qid + 4) * PSTR + mq + grp + 8];
#pragma unroll
            for (int nt = 0; nt < 8; nt++) {
                uint32_t b0 = __float_as_uint(Vsf[(kk + qid    ) * KSTR + nt * 8 + grp]);
                uint32_t b1 = __float_as_uint(Vsf[(kk + qid + 4) * KSTR + nt * 8 + grp]);
                mma_tf32(Oa[nt], a0, a1, a2, a3, b0, b1);
            }
        }
        __syncwarp();
    }

    const float i0 = 1.0f / l0;
    const float i1 = 1.0f / l1;
    float* yp0 = y + (size_t)(b * SEQ + q0 + mq + grp) * DIM + h * HD;
    float* yp1 = yp0 + (size_t)8 * DIM;
#pragma unroll
    for (int nt = 0; nt < 8; nt++) {
        const int d = nt * 8 + (qid << 1);
        float2 v0, v1;
        v0.x = Oa[nt][0] * i0; v0.y = Oa[nt][1] * i0;
        v1.x = Oa[nt][2] * i1; v1.y = Oa[nt][3] * i1;
        *(float2*)(yp0 + d) = v0;
        *(float2*)(yp1 + d) = v1;
    }
}

/* ------------------------------------------------------------------ */
/* launch                                                              */
/* ------------------------------------------------------------------ */
extern "C" void kernel_launch(void* const* d_in, const int* in_sizes, int n_in,
                              void* d_out, int out_size)
{
    (void)in_sizes; (void)n_in; (void)out_size;

    const float* x      = (const float*)d_in[0];
    const int*   mask   = (const int*)  d_in[1];
    const float* ln1_g  = (const float*)d_in[2];
    const float* ln1_b  = (const float*)d_in[3];
    const float* qkv_w  = (const float*)d_in[4];
    const float* proj_w = (const float*)d_in[5];
    const float* proj_b = (const float*)d_in[6];
    const float* ln2_g  = (const float*)d_in[7];
    const float* ln2_b  = (const float*)d_in[8];
    const float* fc1_w  = (const float*)d_in[9];
    const float* fc1_b  = (const float*)d_in[10];
    const float* fc2_w  = (const float*)d_in[11];
    const float* fc2_b  = (const float*)d_in[12];
    float* out = (float*)d_out;

    float *qkv, *y, *x1, *h2, *w1, *w2, *c1a, *c2a, *c1b, *c2b;
    float2* st;
    cudaGetSymbolAddress((void**)&qkv, g_qkv);
    cudaGetSymbolAddress((void**)&y,   g_y);
    cudaGetSymbolAddress((void**)&x1,  g_x1);
    cudaGetSymbolAddress((void**)&h2,  g_h2);
    cudaGetSymbolAddress((void**)&st,  g_stat);
    cudaGetSymbolAddress((void**)&w1,  g_w1);
    cudaGetSymbolAddress((void**)&w2,  g_w2);
    cudaGetSymbolAddress((void**)&c1a, g_c1a);
    cudaGetSymbolAddress((void**)&c2a, g_c2a);
    cudaGetSymbolAddress((void**)&c1b, g_c1b);
    cudaGetSymbolAddress((void**)&c2b, g_c2b);

    /* idempotent, every call (no static guards allowed) */
    cudaFuncSetAttribute(attn_mma_kernel,
                         cudaFuncAttributeMaxDynamicSharedMemorySize,
                         ATT_SMEM_WORDS * 4);

    /* 0. weight transforms (input-only dependencies) */
    prep_w<<<QKV3 / 8, 256>>>(qkv_w, ln1_g, ln1_b, w1, c1a, c2a);
    prep_w<<<HID  / 8, 256>>>(fc1_w, ln2_g, ln2_b, w2, c1b, c2b);

    /* 1. LN1 stats */
    row_stats<<<ROWS / 8, 256>>>(x, st);

    /* 2. qkv = LN1(x) @ qkv_w^T  (exact, via weight transform) */
    gemm_mma<0, 128><<<dim3(QKV3 / 128, ROWS / 128), 256>>>(
        x, w1, nullptr, nullptr, qkv, st, c1a, c2a, ROWS, QKV3, DIM);

    /* 3. y = attention(qkv, mask) */
    attn_mma_kernel<<<dim3(SEQ / 128, BATCH * NH), 256, ATT_SMEM_WORDS * 4>>>(
        qkv, mask, y);

    /* 4. x1 = x + y @ proj_w^T + proj_b */
    gemm_mma<1, 64><<<dim3(DIM / 64, ROWS / 128), 256>>>(
        y, proj_w, proj_b, x, x1, nullptr, nullptr, nullptr, ROWS, DIM, DIM);

    /* 5. LN2 stats */
    row_stats<<<ROWS / 8, 256>>>(x1, st);

    /* 6. h2 = gelu(LN2(x1) @ fc1_w^T + fc1_b) */
    gemm_mma<2, 128><<<dim3(HID / 128, ROWS / 128), 256>>>(
        x1, w2, fc1_b, nullptr, h2, st, c1b, c2b, ROWS, HID, DIM);

    /* 7. out = x1 + h2 @ fc2_w^T + fc2_b */
    gemm_mma<1, 64><<<dim3(DIM / 64, ROWS / 128), 256>>>(
        h2, fc2_w, fc2_b, x1, out, nullptr, nullptr, nullptr, ROWS, DIM, HID);
}

// round 14
// speedup vs baseline: 3.3685x; 1.0752x over previous
#include <cuda_runtime.h>
#include <math.h>
#include <stdint.h>

#define DIM   768
#define QKV3  2304
#define HID   3072
#define NH    12
#define HD    64
#define SEQ   2048
#define BATCH 2
#define ROWS  (BATCH*SEQ)        /* 4096 */
#define LNEPS 1e-5f
#define ATT_SCALE 0.125f         /* 64^-0.5 */

/* ------------------------------------------------------------------ */
/* scratch (device globals; no allocation allowed)                     */
/* ------------------------------------------------------------------ */
__device__ float  g_qkv [ROWS * QKV3];
__device__ float  g_y   [ROWS * DIM];
__device__ float  g_x1  [ROWS * DIM];
__device__ float  g_h2  [ROWS * HID];
__device__ float2 g_stat[ROWS];          /* per-row (mean, rstd)      */
__device__ float  g_w1  [QKV3 * DIM];    /* qkv_w * ln1_g             */
__device__ float  g_w2  [HID * DIM];     /* fc1_w * ln2_g             */
__device__ float  g_c1a [QKV3], g_c2a[QKV3];
__device__ float  g_c1b [HID],  g_c2b[HID];

__device__ __forceinline__ uint32_t f2tf32(float x) {
    uint32_t r;
    asm("cvt.rna.tf32.f32 %0, %1;" : "=r"(r) : "f"(x));
    return r;
}

__device__ __forceinline__ void mma_tf32(float* c,
    uint32_t a0, uint32_t a1, uint32_t a2, uint32_t a3,
    uint32_t b0, uint32_t b1)
{
    asm volatile(
        "mma.sync.aligned.m16n8k8.row.col.f32.tf32.tf32.f32 "
        "{%0,%1,%2,%3}, {%4,%5,%6,%7}, {%8,%9}, {%0,%1,%2,%3};\n"
        : "+f"(c[0]), "+f"(c[1]), "+f"(c[2]), "+f"(c[3])
        : "r"(a0), "r"(a1), "r"(a2), "r"(a3), "r"(b0), "r"(b1));
}

/* ------------------------------------------------------------------ */
/* Row stats: one warp per row -> (mean, rstd)                         */
/* ------------------------------------------------------------------ */
__global__ void __launch_bounds__(256) row_stats(
    const float* __restrict__ x, float2* __restrict__ st)
{
    const int row  = blockIdx.x * 8 + (threadIdx.x >> 5);
    const int lane = threadIdx.x & 31;
    const float* xp = x + (size_t)row * DIM;

    float s = 0.f, ss = 0.f;
#pragma unroll
    for (int i = 0; i < 6; i++) {
        float4 v = *(const float4*)(xp + lane * 4 + i * 128);
        s  += (v.x + v.y) + (v.z + v.w);
        ss += (v.x * v.x + v.y * v.y) + (v.z * v.z + v.w * v.w);
    }
#pragma unroll
    for (int o = 16; o > 0; o >>= 1) {
        s  += __shfl_xor_sync(0xffffffffu, s,  o);
        ss += __shfl_xor_sync(0xffffffffu, ss, o);
    }
    if (lane == 0) {
        float mean = s * (1.0f / DIM);
        float var  = ss * (1.0f / DIM) - mean * mean;
        float2 r; r.x = mean; r.y = rsqrtf(var + LNEPS);
        st[row] = r;
    }
}

/* ------------------------------------------------------------------ */
/* Weight transform: W'[n,k]=w*g, c1[n]=sum W', c2[n]=sum w*b.         */
/* ------------------------------------------------------------------ */
__global__ void __launch_bounds__(256) prep_w(
    const float* __restrict__ w, const float* __restrict__ g,
    const float* __restrict__ b, float* __restrict__ wp,
    float* __restrict__ c1, float* __restrict__ c2)
{
    const int row  = blockIdx.x * 8 + (threadIdx.x >> 5);
    const int lane = threadIdx.x & 31;
    const float* wr = w + (size_t)row * DIM;
    float* wo = wp + (size_t)row * DIM;

    float s1 = 0.f, s2 = 0.f;
#pragma unroll
    for (int i = 0; i < 6; i++) {
        const int c = lane * 4 + i * 128;
        float4 w4 = *(const float4*)(wr + c);
        float4 g4 = *(const float4*)(g + c);
        float4 b4 = *(const float4*)(b + c);
        float4 o;
        o.x = w4.x * g4.x; o.y = w4.y * g4.y;
        o.z = w4.z * g4.z; o.w = w4.w * g4.w;
        s1 += (o.x + o.y) + (o.z + o.w);
        s2 += (w4.x * b4.x + w4.y * b4.y) + (w4.z * b4.z + w4.w * b4.w);
        *(float4*)(wo + c) = o;
    }
#pragma unroll
    for (int o = 16; o > 0; o >>= 1) {
        s1 += __shfl_xor_sync(0xffffffffu, s1, o);
        s2 += __shfl_xor_sync(0xffffffffu, s2, o);
    }
    if (lane == 0) { c1[row] = s1; c2[row] = s2; }
}

/* ------------------------------------------------------------------ */
/* Pure TF32 GEMM. Raw f32 bits into smem (mma truncates to tf32).     */
/* A quad layout: row = (k&3)+4*(k>>3), col = (m>>4)*32+(m&7)*4+mh+km*2*/
/*   -> one LDS.128 per A-fragment, conflict-free reads.               */
/* BM=128, BN in {128,64}. EPI 0: LN-exact (qkv) | 1: +bias+res | 2:   */
/* LN-exact +bias, GELU (fc1).                                         */
/* ------------------------------------------------------------------ */
#define ASTR3 264   /* ==8 mod 32, row start 16B-aligned */

template <int EPI, int BN>
__global__ void __launch_bounds__(256) gemm_mma(
    const float* __restrict__ A, const float* __restrict__ B,
    const float* __restrict__ bias, const float* __restrict__ res,
    float* __restrict__ C, const float2* __restrict__ stats,
    const float* __restrict__ c1v, const float* __restrict__ c2v,
    int M, int N, int K)
{
    constexpr int BSTR_ = (BN == 128) ? 264 : 136;  /* ==8 mod 32 */
    constexpr int MT    = (BN == 128) ? 4 : 2;
    constexpr int WMS   = (BN == 128) ? 64 : 32;
    __shared__ uint32_t As3[2][8][ASTR3];
    __shared__ uint32_t Bs2[2][8][BSTR_];

    const int t    = threadIdx.x;
    const int lane = t & 31;
    const int grp  = lane >> 2;
    const int qid  = lane & 3;
    const int warp = t >> 5;
    const int wm   = (BN == 128) ? (warp >> 2) : (warp >> 1);
    const int wn   = (BN == 128) ? (warp & 3) : (warp & 1);

    const int m0 = blockIdx.y << 7;
    const int n0 = blockIdx.x * BN;

    const int lr = t >> 2;            /* 0..63  */
    const int lk = (t & 3) << 2;      /* 0,4,8,12 */
    const float* Ap0 = A + (size_t)(m0 + lr) * K + lk;
    const float* Ap1 = Ap0 + (size_t)64 * K;
    const float* Bp0 = B + (size_t)(n0 + lr) * K + lk;
    const float* Bp1 = Bp0 + (size_t)64 * K;    /* BN==128 only */

    /* A writer: rows rA..rA+3, cols colA0 (row lr) / colA0+128 (lr+64) */
    const int rA    = (lk >> 3) << 2;            /* 0 or 4 */
    const int kmA   = (lk >> 2) & 1;
    const int colA0 = ((lr >> 4) << 5) + ((lr & 7) << 2)
                    + ((lr >> 3) & 1) + (kmA << 1);
    /* B writer (unchanged scheme) */
    const int brow  = (lk & 8) >> 1;
    const int bbit  = (lk >> 2) & 1;
    const int posB0 = (lr << 1) + bbit;
    const int posB1 = posB0 + 128;

    float acc[MT][4][4];
#pragma unroll
    for (int i = 0; i < MT; i++)
#pragma unroll
        for (int j = 0; j < 4; j++)
#pragma unroll
            for (int r = 0; r < 4; r++) acc[i][j][r] = 0.f;

    float4 pa0 = *(const float4*)Ap0;
    float4 pa1 = *(const float4*)Ap1;
    float4 pb0 = *(const float4*)Bp0;
    float4 pb1;
    if (BN == 128) pb1 = *(const float4*)Bp1;

    int buf = 0;
    {
        As3[0][rA + 0][colA0]       = __float_as_uint(pa0.x);
        As3[0][rA + 1][colA0]       = __float_as_uint(pa0.y);
        As3[0][rA + 2][colA0]       = __float_as_uint(pa0.z);
        As3[0][rA + 3][colA0]       = __float_as_uint(pa0.w);
        As3[0][rA + 0][colA0 + 128] = __float_as_uint(pa1.x);
        As3[0][rA + 1][colA0 + 128] = __float_as_uint(pa1.y);
        As3[0][rA + 2][colA0 + 128] = __float_as_uint(pa1.z);
        As3[0][rA + 3][colA0 + 128] = __float_as_uint(pa1.w);
        Bs2[0][brow + 0][posB0] = __float_as_uint(pb0.x);
        Bs2[0][brow + 1][posB0] = __float_as_uint(pb0.y);
        Bs2[0][brow + 2][posB0] = __float_as_uint(pb0.z);
        Bs2[0][brow + 3][posB0] = __float_as_uint(pb0.w);
        if (BN == 128) {
            Bs2[0][brow + 0][posB1] = __float_as_uint(pb1.x);
            Bs2[0][brow + 1][posB1] = __float_as_uint(pb1.y);
            Bs2[0][brow + 2][posB1] = __float_as_uint(pb1.z);
            Bs2[0][brow + 3][posB1] = __float_as_uint(pb1.w);
        }
    }
    __syncthreads();

    for (int k0 = 16; k0 <= K; k0 += 16) {
        const bool more = (k0 < K);
        if (more) {
            pa0 = *(const float4*)(Ap0 + k0);
            pa1 = *(const float4*)(Ap1 + k0);
            pb0 = *(const float4*)(Bp0 + k0);
            if (BN == 128) pb1 = *(const float4*)(Bp1 + k0);
        }

#pragma unroll
        for (int ks = 0; ks < 2; ks++) {
            uint4 av[MT];
            uint2 bv[4];
#pragma unroll
            for (int mt = 0; mt < MT; mt++) {
                const int mg = wm * (WMS / 16) + mt;
                av[mt] = *(const uint4*)&As3[buf][qid + 4 * ks][mg * 32 + grp * 4];
            }
#pragma unroll
            for (int nt = 0; nt < 4; nt++) {
                const int colB = (wn * 32 + nt * 8 + grp) << 1;
                bv[nt] = *(const uint2*)&Bs2[buf][qid + 4 * ks][colB];
            }
#pragma unroll
            for (int mt = 0; mt < MT; mt++)
#pragma unroll
                for (int nt = 0; nt < 4; nt++)
                    mma_tf32(acc[mt][nt], av[mt].x, av[mt].y,
                             av[mt].z, av[mt].w, bv[nt].x, bv[nt].y);
        }

        if (!more) break;
        buf ^= 1;
        As3[buf][rA + 0][colA0]       = __float_as_uint(pa0.x);
        As3[buf][rA + 1][colA0]       = __float_as_uint(pa0.y);
        As3[buf][rA + 2][colA0]       = __float_as_uint(pa0.z);
        As3[buf][rA + 3][colA0]       = __float_as_uint(pa0.w);
        As3[buf][rA + 0][colA0 + 128] = __float_as_uint(pa1.x);
        As3[buf][rA + 1][colA0 + 128] = __float_as_uint(pa1.y);
        As3[buf][rA + 2][colA0 + 128] = __float_as_uint(pa1.z);
        As3[buf][rA + 3][colA0 + 128] = __float_as_uint(pa1.w);
        Bs2[buf][brow + 0][posB0] = __float_as_uint(pb0.x);
        Bs2[buf][brow + 1][posB0] = __float_as_uint(pb0.y);
        Bs2[buf][brow + 2][posB0] = __float_as_uint(pb0.z);
        Bs2[buf][brow + 3][posB0] = __float_as_uint(pb0.w);
        if (BN == 128) {
            Bs2[buf][brow + 0][posB1] = __float_as_uint(pb1.x);
            Bs2[buf][brow + 1][posB1] = __float_as_uint(pb1.y);
            Bs2[buf][brow + 2][posB1] = __float_as_uint(pb1.z);
            Bs2[buf][brow + 3][posB1] = __float_as_uint(pb1.w);
        }
        __syncthreads();
    }

#pragma unroll
    for (int mt = 0; mt < MT; mt++) {
        const int r0 = m0 + wm * WMS + mt * 16 + grp;
        const int r1 = r0 + 8;
        float rs0 = 0.f, rm0 = 0.f, rs1 = 0.f, rm1 = 0.f;
        if (EPI == 0 || EPI == 2) {
            const float2 s0 = stats[r0];
            const float2 s1 = stats[r1];
            rs0 = s0.y; rm0 = s0.y * s0.x;
            rs1 = s1.y; rm1 = s1.y * s1.x;
        }
#pragma unroll
        for (int nt = 0; nt < 4; nt++) {
            const int n = n0 + wn * 32 + nt * 8 + (qid << 1);
            float2 v0, v1;
            v0.x = acc[mt][nt][0]; v0.y = acc[mt][nt][1];
            v1.x = acc[mt][nt][2]; v1.y = acc[mt][nt][3];
            if (EPI == 0 || EPI == 2) {
                const float2 c1_ = *(const float2*)(c1v + n);
                const float2 c2_ = *(const float2*)(c2v + n);
                v0.x = rs0 * v0.x - rm0 * c1_.x + c2_.x;
                v0.y = rs0 * v0.y - rm0 * c1_.y + c2_.y;
                v1.x = rs1 * v1.x - rm1 * c1_.x + c2_.x;
                v1.y = rs1 * v1.y - rm1 * c1_.y + c2_.y;
            }
            if (EPI == 1 || EPI == 2) {
                const float2 bb = *(const float2*)(bias + n);
                v0.x += bb.x; v0.y += bb.y;
                v1.x += bb.x; v1.y += bb.y;
            }
            if (EPI == 1) {
                const float2 q0 = *(const float2*)(res + (size_t)r0 * N + n);
                const float2 q1 = *(const float2*)(res + (size_t)r1 * N + n);
                v0.x += q0.x; v0.y += q0.y;
                v1.x += q1.x; v1.y += q1.y;
            }
            if (EPI == 2) {
                v0.x = 0.5f * v0.x * (1.0f + erff(v0.x * 0.70710678f));
                v0.y = 0.5f * v0.y * (1.0f + erff(v0.y * 0.70710678f));
                v1.x = 0.5f * v1.x * (1.0f + erff(v1.x * 0.70710678f));
                v1.y = 0.5f * v1.y * (1.0f + erff(v1.y * 0.70710678f));
            }
            *(float2*)(C + (size_t)r0 * N + n) = v0;
            *(float2*)(C + (size_t)r1 * N + n) = v1;
        }
    }
}

/* ------------------------------------------------------------------ */
/* Tensor-core flash attention (TF32 mma) — unchanged from R13 passer. */
/* ------------------------------------------------------------------ */
#define KSTR 72
#define PSTR 136
#define ATT_SMEM_WORDS (64*PSTR + 2*64*KSTR + 64)

__global__ void __launch_bounds__(256) attn_mma_kernel(
    const float* __restrict__ qkv, const int* __restrict__ mask,
    float* __restrict__ y)
{
    extern __shared__ uint32_t smw[];
    uint32_t* Ps  = smw;
    float*    Ksf = (float*)(smw + 64 * PSTR);
    float*    Vsf = Ksf + 64 * KSTR;
    float*    mv  = Vsf + 64 * KSTR;

    const int t    = threadIdx.x;
    const int lane = t & 31;
    const int grp  = lane >> 2;
    const int qid  = lane & 3;
    const int warp = t >> 5;
    const int mq   = warp << 4;

    const int b  = blockIdx.y / NH;
    const int h  = blockIdx.y - b * NH;
    const int q0 = blockIdx.x << 7;

    uint32_t Qf[8][4];
    {
        const float* qp0 = qkv + (size_t)(b * SEQ + q0 + mq + grp) * QKV3 + h * HD;
        const float* qp1 = qp0 + (size_t)8 * QKV3;
#pragma unroll
        for (int ks = 0; ks < 8; ks++) {
            const int d = (ks << 3) + qid;
            Qf[ks][0] = f2tf32(qp0[d]     * ATT_SCALE);
            Qf[ks][1] = f2tf32(qp1[d]     * ATT_SCALE);
            Qf[ks][2] = f2tf32(qp0[d + 4] * ATT_SCALE);
            Qf[ks][3] = f2tf32(qp1[d + 4] * ATT_SCALE);
        }
    }

    float Oa[8][4];
#pragma unroll
    for (int nt = 0; nt < 8; nt++)
#pragma unroll
        for (int r = 0; r < 4; r++) Oa[nt][r] = 0.f;
    float m0 = -1e30f, m1 = -1e30f, l0 = 0.f, l1 = 0.f;

    for (int kt = 0; kt < SEQ; kt += 64) {
        __syncthreads();
        {
            const int kr = t >> 2;
            const int dq = (t & 3) << 4;
            const float* kp = qkv + (size_t)(b * SEQ + kt + kr) * QKV3
                                  + DIM + h * HD + dq;
            const float* vp = kp + DIM;
#pragma unroll
            for (int i = 0; i < 16; i += 4) {
                *(float4*)&Ksf[kr * KSTR + dq + i] = *(const float4*)(kp + i);
                *(float4*)&Vsf[kr * KSTR + dq + i] = *(const float4*)(vp + i);
            }
            if (t < 64) mv[t] = mask[b * SEQ + kt + t] ? -1e30f : 0.f;
        }
        __syncthreads();

        float Sa[8][4];
#pragma unroll
        for (int nt = 0; nt < 8; nt++)
#pragma unroll
            for (int r = 0; r < 4; r++) Sa[nt][r] = 0.f;
#pragma unroll
        for (int ks = 0; ks < 8; ks++) {
            const int kk = ks << 3;
#pragma unroll
            for (int nt = 0; nt < 8; nt++) {
                uint32_t b0 = __float_as_uint(Ksf[(nt * 8 + grp) * KSTR + kk + qid]);
                uint32_t b1 = __float_as_uint(Ksf[(nt * 8 + grp) * KSTR + kk + qid + 4]);
                mma_tf32(Sa[nt], Qf[ks][0], Qf[ks][1], Qf[ks][2], Qf[ks][3],
                         b0, b1);
            }
        }

        float mx0 = -1e30f, mx1 = -1e30f;
#pragma unroll
        for (int nt = 0; nt < 8; nt++) {
            const float a0 = mv[nt * 8 + 2 * qid];
            const float a1 = mv[nt * 8 + 2 * qid + 1];
            Sa[nt][0] += a0; Sa[nt][1] += a1;
            Sa[nt][2] += a0; Sa[nt][3] += a1;
            mx0 = fmaxf(mx0, fmaxf(Sa[nt][0], Sa[nt][1]));
            mx1 = fmaxf(mx1, fmaxf(Sa[nt][2], Sa[nt][3]));
        }
        mx0 = fmaxf(mx0, __shfl_xor_sync(0xffffffffu, mx0, 1));
        mx0 = fmaxf(mx0, __shfl_xor_sync(0xffffffffu, mx0, 2));
        mx1 = fmaxf(mx1, __shfl_xor_sync(0xffffffffu, mx1, 1));
        mx1 = fmaxf(mx1, __shfl_xor_sync(0xffffffffu, mx1, 2));

        const float nm0 = fmaxf(m0, mx0);
        const float nm1 = fmaxf(m1, mx1);
        const float sc0 = __expf(m0 - nm0);
        const float sc1 = __expf(m1 - nm1);
        m0 = nm0; m1 = nm1;

        float s0 = 0.f, s1 = 0.f;
#pragma unroll
        for (int nt = 0; nt < 8; nt++) {
            const float p0 = __expf(Sa[nt][0] - nm0);
            const float p1 = __expf(Sa[nt][1] - nm0);
            const float p2 = __expf(Sa[nt][2] - nm1);
            const float p3 = __expf(Sa[nt][3] - nm1);
            s0 += p0 + p1; s1 += p2 + p3;
            const int kb = nt * 8 + 2 * qid;
            Ps[(kb    ) * PSTR + mq + grp]     = __float_as_uint(p0);
            Ps[(kb + 1) * PSTR + mq + grp]     = __float_as_uint(p1);
            Ps[(kb    ) * PSTR + mq + grp + 8] = __float_as_uint(p2);
            Ps[(kb + 1) * PSTR + mq + grp + 8] = __float_as_uint(p3);
        }
        s0 += __shfl_xor_sync(0xffffffffu, s0, 1);
        s0 += __shfl_xor_sync(0xffffffffu, s0, 2);
        s1 += __shfl_xor_sync(0xffffffffu, s1, 1);
        s1 += __shfl_xor_sync(0xffffffffu, s1, 2);
        l0 = l0 * sc0 + s0;
        l1 = l1 * sc1 + s1;

#pragma unroll
        for (int nt = 0; nt < 8; nt++) {
            Oa[nt][0] *= sc0; Oa[nt][1] *= sc0;
            Oa[nt][2] *= sc1; Oa[nt][3] *= sc1;
        }
        __syncwarp();

#pragma unroll
        for (int ks = 0; ks < 8; ks++) {
            const int kk = ks << 3;
            const uint32_t a0 = Ps[(kk + qid    ) * PSTR + mq + grp];
            const uint32_t a1 = Ps[(kk + qid    ) * PSTR + mq + grp + 8];
            const uint32_t a2 = Ps[(kk + qid + 4) * PSTR + mq + grp];
            const uint32_t a3 = Ps[(kk + qid + 4) * PSTR + mq + grp + 8];
#pragma unroll
            for (int nt = 0; nt < 8; nt++) {
                uint32_t b0 = __float_as_uint(Vsf[(kk + qid    ) * KSTR + nt * 8 + grp]);
                uint32_t b1 = __float_as_uint(Vsf[(kk + qid + 4) * KSTR + nt * 8 + grp]);
                mma_tf32(Oa[nt], a0, a1, a2, a3, b0, b1);
            }
        }
        __syncwarp();
    }

    const float i0 = 1.0f / l0;
    const float i1 = 1.0f / l1;
    float* yp0 = y + (size_t)(b * SEQ + q0 + mq + grp) * DIM + h * HD;
    float* yp1 = yp0 + (size_t)8 * DIM;
#pragma unroll
    for (int nt = 0; nt < 8; nt++) {
        const int d = nt * 8 + (qid << 1);
        float2 v0, v1;
        v0.x = Oa[nt][0] * i0; v0.y = Oa[nt][1] * i0;
        v1.x = Oa[nt][2] * i1; v1.y = Oa[nt][3] * i1;
        *(float2*)(yp0 + d) = v0;
        *(float2*)(yp1 + d) = v1;
    }
}

/* ------------------------------------------------------------------ */
/* launch                                                              */
/* ------------------------------------------------------------------ */
extern "C" void kernel_launch(void* const* d_in, const int* in_sizes, int n_in,
                              void* d_out, int out_size)
{
    (void)in_sizes; (void)n_in; (void)out_size;

    const float* x      = (const float*)d_in[0];
    const int*   mask   = (const int*)  d_in[1];
    const float* ln1_g  = (const float*)d_in[2];
    const float* ln1_b  = (const float*)d_in[3];
    const float* qkv_w  = (const float*)d_in[4];
    const float* proj_w = (const float*)d_in[5];
    const float* proj_b = (const float*)d_in[6];
    const float* ln2_g  = (const float*)d_in[7];
    const float* ln2_b  = (const float*)d_in[8];
    const float* fc1_w  = (const float*)d_in[9];
    const float* fc1_b  = (const float*)d_in[10];
    const float* fc2_w  = (const float*)d_in[11];
    const float* fc2_b  = (const float*)d_in[12];
    float* out = (float*)d_out;

    float *qkv, *y, *x1, *h2, *w1, *w2, *c1a, *c2a, *c1b, *c2b;
    float2* st;
    cudaGetSymbolAddress((void**)&qkv, g_qkv);
    cudaGetSymbolAddress((void**)&y,   g_y);
    cudaGetSymbolAddress((void**)&x1,  g_x1);
    cudaGetSymbolAddress((void**)&h2,  g_h2);
    cudaGetSymbolAddress((void**)&st,  g_stat);
    cudaGetSymbolAddress((void**)&w1,  g_w1);
    cudaGetSymbolAddress((void**)&w2,  g_w2);
    cudaGetSymbolAddress((void**)&c1a, g_c1a);
    cudaGetSymbolAddress((void**)&c2a, g_c2a);
    cudaGetSymbolAddress((void**)&c1b, g_c1b);
    cudaGetSymbolAddress((void**)&c2b, g_c2b);

    /* idempotent, every call (no static guards allowed) */
    cudaFuncSetAttribute(attn_mma_kernel,
                         cudaFuncAttributeMaxDynamicSharedMemorySize,
                         ATT_SMEM_WORDS * 4);

    /* 0. weight transforms (input-only dependencies) */
    prep_w<<<QKV3 / 8, 256>>>(qkv_w, ln1_g, ln1_b, w1, c1a, c2a);
    prep_w<<<HID  / 8, 256>>>(fc1_w, ln2_g, ln2_b, w2, c1b, c2b);

    /* 1. LN1 stats */
    row_stats<<<ROWS / 8, 256>>>(x, st);

    /* 2. qkv = LN1(x) @ qkv_w^T  (exact, via weight transform) */
    gemm_mma<0, 128><<<dim3(QKV3 / 128, ROWS / 128), 256>>>(
        x, w1, nullptr, nullptr, qkv, st, c1a, c2a, ROWS, QKV3, DIM);

    /* 3. y = attention(qkv, mask) */
    attn_mma_kernel<<<dim3(SEQ / 128, BATCH * NH), 256, ATT_SMEM_WORDS * 4>>>(
        qkv, mask, y);

    /* 4. x1 = x + y @ proj_w^T + proj_b */
    gemm_mma<1, 64><<<dim3(DIM / 64, ROWS / 128), 256>>>(
        y, proj_w, proj_b, x, x1, nullptr, nullptr, nullptr, ROWS, DIM, DIM);

    /* 5. LN2 stats */
    row_stats<<<ROWS / 8, 256>>>(x1, st);

    /* 6. h2 = gelu(LN2(x1) @ fc1_w^T + fc1_b) */
    gemm_mma<2, 128><<<dim3(HID / 128, ROWS / 128), 256>>>(
        x1, w2, fc1_b, nullptr, h2, st, c1b, c2b, ROWS, HID, DIM);

    /* 7. out = x1 + h2 @ fc2_w^T + fc2_b */
    gemm_mma<1, 64><<<dim3(DIM / 64, ROWS / 128), 256>>>(
        h2, fc2_w, fc2_b, x1, out, nullptr, nullptr, nullptr, ROWS, DIM, HID);
}